// round 4
// baseline (speedup 1.0000x reference)
#include <cuda_runtime.h>
#include <cstdint>
#include <cstddef>

// ---------------- problem constants ----------------
constexpr int B_   = 2;
constexpr int L_   = 2048;
constexpr int DIM_ = 512;
constexpr int DIN_ = 1024;
constexpr int DST_ = 16;
constexpr int BL_  = B_ * L_;          // 4096 rows
#define LOG2E_F 1.4426950408889634f

// ---------------- scratch (static device globals; no allocation) ----------------
__device__ float g_xn    [(size_t)BL_ * DIM_];        // LN1 output
__device__ float g_ul    [(size_t)BL_ * 2 * DIN_];    // in_proj output [u | z]
__device__ float g_ucf   [(size_t)BL_ * DIN_];        // conv+silu fwd
__device__ float g_ucb   [(size_t)BL_ * DIN_];        // conv+silu bwd (reversed time)
__device__ float g_xdblf [(size_t)BL_ * 64];          // x_proj fwd [dt|B|C]
__device__ float g_xdblb [(size_t)BL_ * 64];
__device__ float g_deltaf[(size_t)BL_ * DIN_];
__device__ float g_deltab[(size_t)BL_ * DIN_];
__device__ float g_ysf   [(size_t)BL_ * DIN_];        // scan output fwd
__device__ float g_ysb   [(size_t)BL_ * DIN_];        // scan output bwd (reversed time)
__device__ float g_yc    [(size_t)BL_ * DIN_];        // combined y
__device__ float g_outpre[(size_t)BL_ * DIM_];        // out_proj output

__device__ __forceinline__ float* get_buf(int id) {
    switch (id) {
        case 0: return g_xn;
        case 1: return g_ul;
        case 2: return g_ucf;
        case 3: return g_ucb;
        case 4: return g_xdblf;
        case 5: return g_xdblb;
        case 6: return g_deltaf;
        case 7: return g_deltab;
        case 8: return g_yc;
        default: return g_outpre;
    }
}

// ---------------- small math helpers ----------------
__device__ __forceinline__ float ex2f_(float x) {
    float y; asm("ex2.approx.ftz.f32 %0, %1;" : "=f"(y) : "f"(x)); return y;
}
__device__ __forceinline__ float silu_f(float x) {
    return x / (1.0f + ex2f_(-LOG2E_F * x));
}
__device__ __forceinline__ float softplus_f(float x) {
    return fmaxf(x, 0.0f) + log1pf(__expf(-fabsf(x)));
}
__device__ __forceinline__ unsigned f2tf(float x) {
    unsigned r; asm("cvt.rna.tf32.f32 %0, %1;" : "=r"(r) : "f"(x)); return r;
}
__device__ __forceinline__ void mma_tf32(float c[4], const unsigned a[4],
                                         unsigned b0, unsigned b1) {
    asm volatile(
        "mma.sync.aligned.m16n8k8.row.col.f32.tf32.tf32.f32 "
        "{%0,%1,%2,%3}, {%4,%5,%6,%7}, {%8,%9}, {%0,%1,%2,%3};"
        : "+f"(c[0]), "+f"(c[1]), "+f"(c[2]), "+f"(c[3])
        : "r"(a[0]), "r"(a[1]), "r"(a[2]), "r"(a[3]), "r"(b0), "r"(b1));
}

// ---------------- LayerNorm (mode 0: LN1 x->g_xn; mode 1: LN2 (g_outpre+x)->out) ----
__global__ __launch_bounds__(128) void ln_kernel(
    const float* __restrict__ x, const float* __restrict__ w,
    const float* __restrict__ bvec, float* __restrict__ outp, int mode)
{
    __shared__ float red[8];
    const int row = blockIdx.x;
    const int tid = threadIdx.x;     // 128 threads, 4 floats each (DIM=512)

    float4 v = reinterpret_cast<const float4*>(x + (size_t)row * DIM_)[tid];
    if (mode) {
        float4 r = reinterpret_cast<const float4*>(g_outpre + (size_t)row * DIM_)[tid];
        v.x += r.x; v.y += r.y; v.z += r.z; v.w += r.w;
    }
    float s  = v.x + v.y + v.z + v.w;
    float ss = v.x*v.x + v.y*v.y + v.z*v.z + v.w*v.w;
    #pragma unroll
    for (int o = 16; o; o >>= 1) {
        s  += __shfl_xor_sync(0xffffffffu, s,  o);
        ss += __shfl_xor_sync(0xffffffffu, ss, o);
    }
    if ((tid & 31) == 0) { red[tid >> 5] = s; red[4 + (tid >> 5)] = ss; }
    __syncthreads();
    s  = red[0] + red[1] + red[2] + red[3];
    ss = red[4] + red[5] + red[6] + red[7];
    const float mean = s * (1.0f / DIM_);
    const float var  = ss * (1.0f / DIM_) - mean * mean;
    const float inv  = rsqrtf(var + 1e-5f);

    float4 wv = reinterpret_cast<const float4*>(w)[tid];
    float4 bv = reinterpret_cast<const float4*>(bvec)[tid];
    float4 o4;
    o4.x = (v.x - mean) * inv * wv.x + bv.x;
    o4.y = (v.y - mean) * inv * wv.y + bv.y;
    o4.z = (v.z - mean) * inv * wv.z + bv.z;
    o4.w = (v.w - mean) * inv * wv.w + bv.w;
    float* dst = mode ? outp : g_xn;
    reinterpret_cast<float4*>(dst + (size_t)row * DIM_)[tid] = o4;
}

// ---------------- tf32 tensor-core GEMM, software-pipelined double buffer --------
// C(M,N) = A(M,K) @ W(N,K)^T. 256 threads, 8 warps.
// BM in {64,128}, BN in {64,128}. Warp tile: 32 x (BN/(8/(BM/32))).
// blockIdx.z selects branch pair (aid0/W0/cid0/b0 vs aid1/...).
// EPI: 0 = none, 1 = +bias[n] then softplus.
template <int BM, int BN, int EPI>
__global__ __launch_bounds__(256) void gemm_tf32_kernel(
    int Kd,
    int aid0, int aid1, int lda,
    const float* __restrict__ W0, const float* __restrict__ W1, int ldw,
    int cid0, int cid1, int ldc,
    const float* __restrict__ b0p, const float* __restrict__ b1p)
{
    constexpr int WARPS_M = BM / 32;
    constexpr int WARPS_N = 8 / WARPS_M;
    constexpr int WTN = BN / WARPS_N;      // warp tile in n
    constexpr int NF  = WTN / 8;           // n-frags per warp
    constexpr int AF4 = BM * 4 / 256;      // float4 tile-loads per thread (A)
    constexpr int WF4 = BN * 4 / 256;
    constexpr int SST = 20;                // smem row stride (pad 16 -> 20)

    __shared__ __align__(16) unsigned sA[2][BM * SST];
    __shared__ __align__(16) unsigned sW[2][BN * SST];

    const int z = blockIdx.z;
    const float* __restrict__ A    = get_buf(z ? aid1 : aid0);
    float* __restrict__ C          = get_buf(z ? cid1 : cid0);
    const float* __restrict__ W    = z ? W1 : W0;
    const float* __restrict__ bias = z ? b1p : b0p;

    const int tid  = threadIdx.x;
    const int lane = tid & 31;
    const int warp = tid >> 5;
    const int g    = lane >> 2;
    const int tig  = lane & 3;
    const int wm   = warp % WARPS_M;
    const int wn   = warp / WARPS_M;
    const int m0   = blockIdx.y * BM;
    const int n0   = blockIdx.x * BN;

    float acc[2][NF][4];
    #pragma unroll
    for (int i = 0; i < 2; i++)
        #pragma unroll
        for (int j = 0; j < NF; j++)
            #pragma unroll
            for (int q = 0; q < 4; q++) acc[i][j][q] = 0.0f;

    float4 aReg[AF4], wReg[WF4];

    auto ldTile = [&](int k0) {
        #pragma unroll
        for (int i = 0; i < AF4; i++) {
            const int idx = tid + i * 256;
            const int r = idx >> 2, kk = (idx & 3) * 4;
            aReg[i] = *reinterpret_cast<const float4*>(A + (size_t)(m0 + r) * lda + k0 + kk);
        }
        #pragma unroll
        for (int i = 0; i < WF4; i++) {
            const int idx = tid + i * 256;
            const int r = idx >> 2, kk = (idx & 3) * 4;
            wReg[i] = *reinterpret_cast<const float4*>(W + (size_t)(n0 + r) * ldw + k0 + kk);
        }
    };
    auto stTile = [&](int buf) {
        #pragma unroll
        for (int i = 0; i < AF4; i++) {
            const int idx = tid + i * 256;
            const int r = idx >> 2, kk = (idx & 3) * 4;
            *reinterpret_cast<uint4*>(&sA[buf][r * SST + kk]) =
                make_uint4(f2tf(aReg[i].x), f2tf(aReg[i].y), f2tf(aReg[i].z), f2tf(aReg[i].w));
        }
        #pragma unroll
        for (int i = 0; i < WF4; i++) {
            const int idx = tid + i * 256;
            const int r = idx >> 2, kk = (idx & 3) * 4;
            *reinterpret_cast<uint4*>(&sW[buf][r * SST + kk]) =
                make_uint4(f2tf(wReg[i].x), f2tf(wReg[i].y), f2tf(wReg[i].z), f2tf(wReg[i].w));
        }
    };
    auto compute = [&](int buf) {
        #pragma unroll
        for (int ks = 0; ks < 16; ks += 8) {
            unsigned af[2][4];
            #pragma unroll
            for (int im = 0; im < 2; im++) {
                const int base = (wm * 32 + im * 16 + g) * SST + ks;
                af[im][0] = sA[buf][base + tig];
                af[im][1] = sA[buf][base + 8 * SST + tig];
                af[im][2] = sA[buf][base + 4 + tig];
                af[im][3] = sA[buf][base + 8 * SST + 4 + tig];
            }
            #pragma unroll
            for (int in = 0; in < NF; in++) {
                const int nb = (wn * WTN + in * 8 + g) * SST + ks;
                const unsigned bf0 = sW[buf][nb + tig];
                const unsigned bf1 = sW[buf][nb + 4 + tig];
                #pragma unroll
                for (int im = 0; im < 2; im++)
                    mma_tf32(acc[im][in], af[im], bf0, bf1);
            }
        }
    };

    // software pipeline: LDG(k+1) || MMA(k), then convert+STS(k+1)
    int buf = 0;
    ldTile(0);
    stTile(0);
    __syncthreads();
    for (int k0 = 0; k0 < Kd; k0 += 16) {
        const bool more = (k0 + 16) < Kd;
        if (more) ldTile(k0 + 16);
        compute(buf);
        if (more) stTile(buf ^ 1);
        __syncthreads();
        buf ^= 1;
    }

    // epilogue
    #pragma unroll
    for (int im = 0; im < 2; im++) {
        #pragma unroll
        for (int in = 0; in < NF; in++) {
            const int row = m0 + wm * 32 + im * 16 + g;
            const int col = n0 + wn * WTN + in * 8 + 2 * tig;
            float v0 = acc[im][in][0], v1 = acc[im][in][1];
            float v2 = acc[im][in][2], v3 = acc[im][in][3];
            if (EPI == 1) {
                const float bc0 = bias[col], bc1 = bias[col + 1];
                v0 = softplus_f(v0 + bc0); v1 = softplus_f(v1 + bc1);
                v2 = softplus_f(v2 + bc0); v3 = softplus_f(v3 + bc1);
            }
            *reinterpret_cast<float2*>(&C[(size_t)row * ldc + col])       = make_float2(v0, v1);
            *reinterpret_cast<float2*>(&C[(size_t)(row + 8) * ldc + col]) = make_float2(v2, v3);
        }
    }
}

// ---------------- depthwise causal conv (K=4) + SiLU, both branches ----------------
__global__ __launch_bounds__(256) void conv_silu_kernel(
    const float* __restrict__ wf, const float* __restrict__ biasf,
    const float* __restrict__ wb, const float* __restrict__ biasb)
{
    const int br = blockIdx.y;
    const int i  = blockIdx.x * 256 + threadIdx.x;     // over BL*DIN
    const int d  = i & (DIN_ - 1);
    const int t  = (i >> 10) & (L_ - 1);
    const int b  = i >> 21;

    const float* w = br ? wb : wf;
    float acc = (br ? biasb : biasf)[d];
    #pragma unroll
    for (int k = 0; k < 4; k++) {
        const int s = t - 3 + k;
        if (s >= 0) {
            const int tt = br ? (L_ - 1 - s) : s;
            acc += w[d * 4 + k] * g_ul[((size_t)(b * L_ + tt) << 11) + d];  // u = ul[:, :DIN]
        }
    }
    const float r = silu_f(acc);
    float* out = br ? g_ucb : g_ucf;
    out[((size_t)(b * L_ + t) << 10) + d] = r;
}

// ---------------- selective scan ----------------
__global__ __launch_bounds__(512) void scan_kernel(
    const float* __restrict__ AlogF, const float* __restrict__ AlogB)
{
    const int br = blockIdx.z;
    const int b  = blockIdx.y;
    const int d0 = blockIdx.x * 32;
    const int tid = threadIdx.x;
    const int n  = tid & 15;
    const int dl = tid >> 4;
    const int d  = d0 + dl;

    const float* __restrict__ delta = br ? g_deltab : g_deltaf;
    const float* __restrict__ xdbl  = br ? g_xdblb  : g_xdblf;
    const float* __restrict__ uc    = br ? g_ucb    : g_ucf;
    const float* __restrict__ Alog  = br ? AlogB    : AlogF;
    float* __restrict__ ys          = br ? g_ysb    : g_ysf;

    const float AL2 = -__expf(Alog[d * DST_ + n]) * LOG2E_F;

    __shared__ float sdelta[64][33];
    __shared__ float sdu[64][33];
    __shared__ float sbc[64][32];   // [ B(0..15) | C(16..31) ]
    __shared__ float sy[64][33];

    float h = 0.0f;

    for (int t0 = 0; t0 < L_; t0 += 64) {
        #pragma unroll
        for (int i = tid; i < 64 * 32; i += 512) {
            const int tt = i >> 5, c = i & 31;
            const size_t gi = ((size_t)(b * L_ + t0 + tt) << 10) + d0 + c;
            const float dv = delta[gi];
            sdelta[tt][c] = dv;
            sdu[tt][c]    = dv * uc[gi];
            sbc[tt][c]    = xdbl[((size_t)(b * L_ + t0 + tt) << 6) + 32 + c];
        }
        __syncthreads();

        #pragma unroll 8
        for (int tt = 0; tt < 64; tt++) {
            const float dv  = sdelta[tt][dl];
            const float du  = sdu[tt][dl];
            const float bb  = sbc[tt][n];
            const float cc  = sbc[tt][16 + n];
            const float e   = ex2f_(dv * AL2);
            h = fmaf(e, h, du * bb);
            float p = h * cc;
            p += __shfl_xor_sync(0xffffffffu, p, 1);
            p += __shfl_xor_sync(0xffffffffu, p, 2);
            p += __shfl_xor_sync(0xffffffffu, p, 4);
            p += __shfl_xor_sync(0xffffffffu, p, 8);
            if (n == 0) sy[tt][dl] = p;
        }
        __syncthreads();

        #pragma unroll
        for (int i = tid; i < 64 * 32; i += 512) {
            const int tt = i >> 5, c = i & 31;
            ys[((size_t)(b * L_ + t0 + tt) << 10) + d0 + c] = sy[tt][c];
        }
    }
}

// ---------------- combine: yc = g*(ys_f + uc_f*D_f + rev(ys_b + uc_b*D_b)) -------
__global__ __launch_bounds__(256) void combine_kernel(
    const float* __restrict__ Df, const float* __restrict__ Db)
{
    const int i = blockIdx.x * 256 + threadIdx.x;      // over BL*DIN
    const int d = i & (DIN_ - 1);
    const int t = (i >> 10) & (L_ - 1);
    const int b = i >> 21;

    const float z  = g_ul[((size_t)(b * L_ + t) << 11) + DIN_ + d];
    const float gg = silu_f(z);
    const size_t fi = (size_t)i;
    const size_t bi = ((size_t)(b * L_ + (L_ - 1 - t)) << 10) + d;
    const float yf = g_ysf[fi] + g_ucf[fi] * Df[d];
    const float yr = g_ysb[bi] + g_ucb[bi] * Db[d];
    g_yc[fi] = gg * (yf + yr);
}

// ---------------- launch ----------------
extern "C" void kernel_launch(void* const* d_in, const int* in_sizes, int n_in,
                              void* d_out, int out_size)
{
    const float* x          = (const float*)d_in[0];
    const float* ln1_w      = (const float*)d_in[1];
    const float* ln1_b      = (const float*)d_in[2];
    const float* ln2_w      = (const float*)d_in[3];
    const float* ln2_b      = (const float*)d_in[4];
    const float* in_proj_w  = (const float*)d_in[5];
    const float* conv_w_fw  = (const float*)d_in[6];
    const float* conv_b_fw  = (const float*)d_in[7];
    const float* xproj_w_fw = (const float*)d_in[8];
    const float* dt_w_fw    = (const float*)d_in[9];
    const float* dt_b_fw    = (const float*)d_in[10];
    const float* A_log_fw   = (const float*)d_in[11];
    const float* D_fw       = (const float*)d_in[12];
    const float* conv_w_bw  = (const float*)d_in[13];
    const float* conv_b_bw  = (const float*)d_in[14];
    const float* xproj_w_bw = (const float*)d_in[15];
    const float* dt_w_bw    = (const float*)d_in[16];
    const float* dt_b_bw    = (const float*)d_in[17];
    const float* A_log_bw   = (const float*)d_in[18];
    const float* D_bw       = (const float*)d_in[19];
    const float* out_proj_w = (const float*)d_in[20];
    float* out = (float*)d_out;

    // 1) LN1: x -> g_xn
    ln_kernel<<<BL_, 128>>>(x, ln1_w, ln1_b, nullptr, 0);

    // 2) in_proj: g_xn(4096,512) @ in_proj_w(2048,512)^T -> g_ul(4096,2048)
    gemm_tf32_kernel<128, 128, 0><<<dim3(2048 / 128, BL_ / 128, 1), 256>>>(
        512, /*A*/0, 0, 512, in_proj_w, in_proj_w, 512, /*C*/1, 1, 2048,
        nullptr, nullptr);

    // 3) causal conv + SiLU, fwd + bwd(reversed)
    conv_silu_kernel<<<dim3((BL_ * DIN_) / 256, 2), 256>>>(
        conv_w_fw, conv_b_fw, conv_w_bw, conv_b_bw);

    // 4) x_proj both branches fused (z): uc(4096,1024) @ xproj_w(64,1024)^T
    gemm_tf32_kernel<64, 64, 0><<<dim3(1, BL_ / 64, 2), 256>>>(
        1024, /*A*/2, 3, 1024, xproj_w_fw, xproj_w_bw, 1024, /*C*/4, 5, 64,
        nullptr, nullptr);

    // 5) delta both branches fused: softplus(dt(4096,32) @ dt_w(1024,32)^T + b)
    gemm_tf32_kernel<128, 128, 1><<<dim3(1024 / 128, BL_ / 128, 2), 256>>>(
        32, /*A*/4, 5, 64, dt_w_fw, dt_w_bw, 32, /*C*/6, 7, 1024,
        dt_b_fw, dt_b_bw);

    // 6) selective scans (both branches concurrent via grid.z)
    scan_kernel<<<dim3(DIN_ / 32, B_, 2), 512>>>(A_log_fw, A_log_bw);

    // 7) combine with gate g = silu(z)
    combine_kernel<<<(BL_ * DIN_) / 256, 256>>>(D_fw, D_bw);

    // 8) out_proj: g_yc(4096,1024) @ out_proj_w(512,1024)^T -> g_outpre(4096,512)
    gemm_tf32_kernel<128, 64, 0><<<dim3(512 / 64, BL_ / 128, 1), 256>>>(
        1024, /*A*/8, 8, 1024, out_proj_w, out_proj_w, 1024, /*C*/9, 9, 512,
        nullptr, nullptr);

    // 9) LN2(residual + out_pre) -> d_out
    ln_kernel<<<BL_, 128>>>(x, ln2_w, ln2_b, out, 1);
}

// round 6
// speedup vs baseline: 1.7608x; 1.7608x over previous
#include <cuda_runtime.h>
#include <cstdint>
#include <cstddef>

// ---------------- problem constants ----------------
constexpr int B_   = 2;
constexpr int L_   = 2048;
constexpr int DIM_ = 512;
constexpr int DIN_ = 1024;
constexpr int DST_ = 16;
constexpr int BL_  = B_ * L_;          // 4096 rows
#define LOG2E_F 1.4426950408889634f

// ---------------- scratch (static device globals; no allocation) ----------------
__device__ float g_xn    [(size_t)BL_ * DIM_];        // LN1 output
__device__ float g_ul    [(size_t)BL_ * 2 * DIN_];    // in_proj output [u | z]
__device__ float g_ucf   [(size_t)BL_ * DIN_];        // conv+silu fwd
__device__ float g_ucb   [(size_t)BL_ * DIN_];        // conv+silu bwd (reversed time)
__device__ float g_xdblf [(size_t)BL_ * 64];          // x_proj fwd [dt|B|C]
__device__ float g_xdblb [(size_t)BL_ * 64];
__device__ float g_deltaf[(size_t)BL_ * DIN_];
__device__ float g_deltab[(size_t)BL_ * DIN_];
__device__ float g_ysf   [(size_t)BL_ * DIN_];        // scan output fwd
__device__ float g_ysb   [(size_t)BL_ * DIN_];        // scan output bwd (reversed time)
__device__ float g_yc    [(size_t)BL_ * DIN_];        // combined y
__device__ float g_outpre[(size_t)BL_ * DIM_];        // out_proj output
__device__ float g_part  [(size_t)4194304];           // split-K partials (16 MB)

__device__ __forceinline__ float* get_buf(int id) {
    switch (id) {
        case 0: return g_xn;
        case 1: return g_ul;
        case 2: return g_ucf;
        case 3: return g_ucb;
        case 4: return g_xdblf;
        case 5: return g_xdblb;
        case 6: return g_deltaf;
        case 7: return g_deltab;
        case 8: return g_yc;
        default: return g_outpre;
    }
}

// ---------------- small math helpers ----------------
__device__ __forceinline__ float ex2f_(float x) {
    float y; asm("ex2.approx.ftz.f32 %0, %1;" : "=f"(y) : "f"(x)); return y;
}
__device__ __forceinline__ float silu_f(float x) {
    return x / (1.0f + ex2f_(-LOG2E_F * x));
}
__device__ __forceinline__ float softplus_f(float x) {
    return fmaxf(x, 0.0f) + log1pf(__expf(-fabsf(x)));
}
__device__ __forceinline__ void mma_tf32(float c[4], const unsigned a[4],
                                         unsigned b0, unsigned b1) {
    asm volatile(
        "mma.sync.aligned.m16n8k8.row.col.f32.tf32.tf32.f32 "
        "{%0,%1,%2,%3}, {%4,%5,%6,%7}, {%8,%9}, {%0,%1,%2,%3};"
        : "+f"(c[0]), "+f"(c[1]), "+f"(c[2]), "+f"(c[3])
        : "r"(a[0]), "r"(a[1]), "r"(a[2]), "r"(a[3]), "r"(b0), "r"(b1));
}
__device__ __forceinline__ void cp16(uint32_t smem_dst, const void* gsrc) {
    asm volatile("cp.async.cg.shared.global [%0], [%1], 16;"
                 :: "r"(smem_dst), "l"(gsrc));
}
#define CP_COMMIT()  asm volatile("cp.async.commit_group;")
#define CP_WAIT0()   asm volatile("cp.async.wait_group 0;")

// ---------------- LayerNorm (mode 0: LN1 x->g_xn; mode 1: LN2 (g_outpre+x)->out) ----
__global__ __launch_bounds__(128) void ln_kernel(
    const float* __restrict__ x, const float* __restrict__ w,
    const float* __restrict__ bvec, float* __restrict__ outp, int mode)
{
    __shared__ float red[8];
    const int row = blockIdx.x;
    const int tid = threadIdx.x;     // 128 threads, 4 floats each (DIM=512)

    float4 v = reinterpret_cast<const float4*>(x + (size_t)row * DIM_)[tid];
    if (mode) {
        float4 r = reinterpret_cast<const float4*>(g_outpre + (size_t)row * DIM_)[tid];
        v.x += r.x; v.y += r.y; v.z += r.z; v.w += r.w;
    }
    float s  = v.x + v.y + v.z + v.w;
    float ss = v.x*v.x + v.y*v.y + v.z*v.z + v.w*v.w;
    #pragma unroll
    for (int o = 16; o; o >>= 1) {
        s  += __shfl_xor_sync(0xffffffffu, s,  o);
        ss += __shfl_xor_sync(0xffffffffu, ss, o);
    }
    if ((tid & 31) == 0) { red[tid >> 5] = s; red[4 + (tid >> 5)] = ss; }
    __syncthreads();
    s  = red[0] + red[1] + red[2] + red[3];
    ss = red[4] + red[5] + red[6] + red[7];
    const float mean = s * (1.0f / DIM_);
    const float var  = ss * (1.0f / DIM_) - mean * mean;
    const float inv  = rsqrtf(var + 1e-5f);

    float4 wv = reinterpret_cast<const float4*>(w)[tid];
    float4 bv = reinterpret_cast<const float4*>(bvec)[tid];
    float4 o4;
    o4.x = (v.x - mean) * inv * wv.x + bv.x;
    o4.y = (v.y - mean) * inv * wv.y + bv.y;
    o4.z = (v.z - mean) * inv * wv.z + bv.z;
    o4.w = (v.w - mean) * inv * wv.w + bv.w;
    float* dst = mode ? outp : g_xn;
    reinterpret_cast<float4*>(dst + (size_t)row * DIM_)[tid] = o4;
}

// ---------------- tf32 tensor-core GEMM with cp.async double buffer -------------
// C(M,N) = A(M,K) @ W(N,K)^T. 256 threads, 8 warps.
// MODE 0: blockIdx.z selects branch {aid0/W0/cid0/b0, aid1/...}, full K.
// MODE 1: split-K. blockIdx.z = branch*nsplit + ks; K range [ks*kchunk, ...);
//         output partial to part[(z*Mtot + row)*ldc + col].
// Raw fp32 is staged to smem; tf32 MMA truncates mantissa in hardware.
// EPI: 0 = none, 1 = +bias[n] then softplus.
template <int BM, int BN, int EPI, int MODE>
__global__ __launch_bounds__(256) void gemm_tc(
    int Kd, int kchunk, int nsplit,
    int aid0, int aid1, int lda,
    const float* __restrict__ W0, const float* __restrict__ W1, int ldw,
    int cid0, int cid1, int ldc,
    const float* __restrict__ b0p, const float* __restrict__ b1p)
{
    constexpr int WARPS_M = BM / 32;
    constexpr int WARPS_N = 8 / WARPS_M;
    constexpr int WTN = BN / WARPS_N;          // warp tile n
    constexpr int NF  = WTN / 8;               // n-frags per warp
    constexpr int AF4 = BM / 64;               // 16B copies/thread for A tile
    constexpr int WF4 = BN / 64;
    constexpr int SST = 20;                    // smem row stride (floats)

    __shared__ __align__(16) float sA[2][BM * SST];
    __shared__ __align__(16) float sW[2][BN * SST];

    const int z = blockIdx.z;
    int br, k_begin, k_end;
    if (MODE == 1) { br = z / nsplit; const int ks = z - br * nsplit;
                     k_begin = ks * kchunk; k_end = k_begin + kchunk; }
    else           { br = z; k_begin = 0; k_end = Kd; }

    const float* __restrict__ A    = get_buf(br ? aid1 : aid0);
    const float* __restrict__ W    = br ? W1 : W0;
    const float* __restrict__ bias = br ? b1p : b0p;

    const int tid  = threadIdx.x;
    const int lane = tid & 31;
    const int warp = tid >> 5;
    const int g    = lane >> 2;
    const int tig  = lane & 3;
    const int wm   = warp % WARPS_M;
    const int wn   = warp / WARPS_M;
    const int m0   = blockIdx.y * BM;
    const int n0   = blockIdx.x * BN;
    const int Mtot = gridDim.y * BM;

    const uint32_t sAb = (uint32_t)__cvta_generic_to_shared(&sA[0][0]);
    const uint32_t sWb = (uint32_t)__cvta_generic_to_shared(&sW[0][0]);

    float acc[2][NF][4];
    #pragma unroll
    for (int i = 0; i < 2; i++)
        #pragma unroll
        for (int j = 0; j < NF; j++)
            #pragma unroll
            for (int q = 0; q < 4; q++) acc[i][j][q] = 0.0f;

    auto ldTileAsync = [&](int k0, int bufi) {
        #pragma unroll
        for (int i = 0; i < AF4; i++) {
            const int idx = tid + i * 256;
            const int r = idx >> 2, kk = (idx & 3) * 4;
            cp16(sAb + (uint32_t)(bufi * BM * SST + r * SST + kk) * 4,
                 A + (size_t)(m0 + r) * lda + k0 + kk);
        }
        #pragma unroll
        for (int i = 0; i < WF4; i++) {
            const int idx = tid + i * 256;
            const int r = idx >> 2, kk = (idx & 3) * 4;
            cp16(sWb + (uint32_t)(bufi * BN * SST + r * SST + kk) * 4,
                 W + (size_t)(n0 + r) * ldw + k0 + kk);
        }
    };
    auto compute = [&](int bufi) {
        const unsigned* uA = reinterpret_cast<const unsigned*>(&sA[bufi][0]);
        const unsigned* uW = reinterpret_cast<const unsigned*>(&sW[bufi][0]);
        #pragma unroll
        for (int ks = 0; ks < 16; ks += 8) {
            unsigned af[2][4];
            #pragma unroll
            for (int im = 0; im < 2; im++) {
                const int base = (wm * 32 + im * 16 + g) * SST + ks;
                af[im][0] = uA[base + tig];
                af[im][1] = uA[base + 8 * SST + tig];
                af[im][2] = uA[base + 4 + tig];
                af[im][3] = uA[base + 8 * SST + 4 + tig];
            }
            #pragma unroll
            for (int in = 0; in < NF; in++) {
                const int nb = (wn * WTN + in * 8 + g) * SST + ks;
                const unsigned bf0 = uW[nb + tig];
                const unsigned bf1 = uW[nb + 4 + tig];
                #pragma unroll
                for (int im = 0; im < 2; im++)
                    mma_tf32(acc[im][in], af[im], bf0, bf1);
            }
        }
    };

    // pipeline: copy(k+1) overlaps MMA(k)
    ldTileAsync(k_begin, 0);
    CP_COMMIT();
    int buf = 0;
    for (int k0 = k_begin; k0 < k_end; k0 += 16) {
        CP_WAIT0();
        __syncthreads();
        if (k0 + 16 < k_end) { ldTileAsync(k0 + 16, buf ^ 1); CP_COMMIT(); }
        compute(buf);
        buf ^= 1;
    }

    // epilogue
    float* __restrict__ Cp;
    if (MODE == 1) Cp = g_part + (size_t)z * (size_t)Mtot * ldc;
    else           Cp = get_buf(br ? cid1 : cid0);

    #pragma unroll
    for (int im = 0; im < 2; im++) {
        #pragma unroll
        for (int in = 0; in < NF; in++) {
            const int row = m0 + wm * 32 + im * 16 + g;
            const int col = n0 + wn * WTN + in * 8 + 2 * tig;
            float v0 = acc[im][in][0], v1 = acc[im][in][1];
            float v2 = acc[im][in][2], v3 = acc[im][in][3];
            if (EPI == 1) {
                const float bc0 = bias[col], bc1 = bias[col + 1];
                v0 = softplus_f(v0 + bc0); v1 = softplus_f(v1 + bc1);
                v2 = softplus_f(v2 + bc0); v3 = softplus_f(v3 + bc1);
            }
            *reinterpret_cast<float2*>(&Cp[(size_t)row * ldc + col])       = make_float2(v0, v1);
            *reinterpret_cast<float2*>(&Cp[(size_t)(row + 8) * ldc + col]) = make_float2(v2, v3);
        }
    }
}

// ---------------- split-K reduce: dst[br] = sum_s part[br*nsplit + s] ------------
// elems4 = rows*cols/4 per branch slab. grid covers nbranch*elems4 threads.
__global__ __launch_bounds__(256) void reduce_split_kernel(
    int nsplit, int elems4, int dst0, int dst1)
{
    const int i = blockIdx.x * 256 + threadIdx.x;
    const int br = i / elems4;
    const int off = i - br * elems4;
    const float4* p = reinterpret_cast<const float4*>(g_part)
                    + (size_t)(br * nsplit) * elems4 + off;
    float4 a = p[0];
    for (int s = 1; s < nsplit; s++) {
        const float4 v = p[(size_t)s * elems4];
        a.x += v.x; a.y += v.y; a.z += v.z; a.w += v.w;
    }
    reinterpret_cast<float4*>(get_buf(br ? dst1 : dst0))[off] = a;
}

// ---------------- depthwise causal conv (K=4) + SiLU, both branches ----------------
__global__ __launch_bounds__(256) void conv_silu_kernel(
    const float* __restrict__ wf, const float* __restrict__ biasf,
    const float* __restrict__ wb, const float* __restrict__ biasb)
{
    const int br = blockIdx.y;
    const int i  = blockIdx.x * 256 + threadIdx.x;     // over BL*DIN
    const int d  = i & (DIN_ - 1);
    const int t  = (i >> 10) & (L_ - 1);
    const int b  = i >> 21;

    const float* w = br ? wb : wf;
    float acc = (br ? biasb : biasf)[d];
    #pragma unroll
    for (int k = 0; k < 4; k++) {
        const int s = t - 3 + k;
        if (s >= 0) {
            const int tt = br ? (L_ - 1 - s) : s;
            acc += w[d * 4 + k] * g_ul[((size_t)(b * L_ + tt) << 11) + d];  // u = ul[:, :DIN]
        }
    }
    const float r = silu_f(acc);
    float* out = br ? g_ucb : g_ucf;
    out[((size_t)(b * L_ + t) << 10) + d] = r;
}

// ---------------- selective scan ----------------
__global__ __launch_bounds__(512) void scan_kernel(
    const float* __restrict__ AlogF, const float* __restrict__ AlogB)
{
    const int br = blockIdx.z;
    const int b  = blockIdx.y;
    const int d0 = blockIdx.x * 32;
    const int tid = threadIdx.x;
    const int n  = tid & 15;
    const int dl = tid >> 4;
    const int d  = d0 + dl;

    const float* __restrict__ delta = br ? g_deltab : g_deltaf;
    const float* __restrict__ xdbl  = br ? g_xdblb  : g_xdblf;
    const float* __restrict__ uc    = br ? g_ucb    : g_ucf;
    const float* __restrict__ Alog  = br ? AlogB    : AlogF;
    float* __restrict__ ys          = br ? g_ysb    : g_ysf;

    const float AL2 = -__expf(Alog[d * DST_ + n]) * LOG2E_F;

    __shared__ float sdelta[64][33];
    __shared__ float sdu[64][33];
    __shared__ float sbc[64][32];   // [ B(0..15) | C(16..31) ]
    __shared__ float sy[64][33];

    float h = 0.0f;

    for (int t0 = 0; t0 < L_; t0 += 64) {
        #pragma unroll
        for (int i = tid; i < 64 * 32; i += 512) {
            const int tt = i >> 5, c = i & 31;
            const size_t gi = ((size_t)(b * L_ + t0 + tt) << 10) + d0 + c;
            const float dv = delta[gi];
            sdelta[tt][c] = dv;
            sdu[tt][c]    = dv * uc[gi];
            sbc[tt][c]    = xdbl[((size_t)(b * L_ + t0 + tt) << 6) + 32 + c];
        }
        __syncthreads();

        #pragma unroll 8
        for (int tt = 0; tt < 64; tt++) {
            const float dv  = sdelta[tt][dl];
            const float du  = sdu[tt][dl];
            const float bb  = sbc[tt][n];
            const float cc  = sbc[tt][16 + n];
            const float e   = ex2f_(dv * AL2);
            h = fmaf(e, h, du * bb);
            float p = h * cc;
            p += __shfl_xor_sync(0xffffffffu, p, 1);
            p += __shfl_xor_sync(0xffffffffu, p, 2);
            p += __shfl_xor_sync(0xffffffffu, p, 4);
            p += __shfl_xor_sync(0xffffffffu, p, 8);
            if (n == 0) sy[tt][dl] = p;
        }
        __syncthreads();

        #pragma unroll
        for (int i = tid; i < 64 * 32; i += 512) {
            const int tt = i >> 5, c = i & 31;
            ys[((size_t)(b * L_ + t0 + tt) << 10) + d0 + c] = sy[tt][c];
        }
    }
}

// ---------------- combine: yc = g*(ys_f + uc_f*D_f + rev(ys_b + uc_b*D_b)) -------
__global__ __launch_bounds__(256) void combine_kernel(
    const float* __restrict__ Df, const float* __restrict__ Db)
{
    const int i = blockIdx.x * 256 + threadIdx.x;      // over BL*DIN
    const int d = i & (DIN_ - 1);
    const int t = (i >> 10) & (L_ - 1);
    const int b = i >> 21;

    const float z  = g_ul[((size_t)(b * L_ + t) << 11) + DIN_ + d];
    const float gg = silu_f(z);
    const size_t fi = (size_t)i;
    const size_t bi = ((size_t)(b * L_ + (L_ - 1 - t)) << 10) + d;
    const float yf = g_ysf[fi] + g_ucf[fi] * Df[d];
    const float yr = g_ysb[bi] + g_ucb[bi] * Db[d];
    g_yc[fi] = gg * (yf + yr);
}

// ---------------- launch ----------------
extern "C" void kernel_launch(void* const* d_in, const int* in_sizes, int n_in,
                              void* d_out, int out_size)
{
    const float* x          = (const float*)d_in[0];
    const float* ln1_w      = (const float*)d_in[1];
    const float* ln1_b      = (const float*)d_in[2];
    const float* ln2_w      = (const float*)d_in[3];
    const float* ln2_b      = (const float*)d_in[4];
    const float* in_proj_w  = (const float*)d_in[5];
    const float* conv_w_fw  = (const float*)d_in[6];
    const float* conv_b_fw  = (const float*)d_in[7];
    const float* xproj_w_fw = (const float*)d_in[8];
    const float* dt_w_fw    = (const float*)d_in[9];
    const float* dt_b_fw    = (const float*)d_in[10];
    const float* A_log_fw   = (const float*)d_in[11];
    const float* D_fw       = (const float*)d_in[12];
    const float* conv_w_bw  = (const float*)d_in[13];
    const float* conv_b_bw  = (const float*)d_in[14];
    const float* xproj_w_bw = (const float*)d_in[15];
    const float* dt_w_bw    = (const float*)d_in[16];
    const float* dt_b_bw    = (const float*)d_in[17];
    const float* A_log_bw   = (const float*)d_in[18];
    const float* D_bw       = (const float*)d_in[19];
    const float* out_proj_w = (const float*)d_in[20];
    float* out = (float*)d_out;

    // 1) LN1: x -> g_xn
    ln_kernel<<<BL_, 128>>>(x, ln1_w, ln1_b, nullptr, 0);

    // 2) in_proj: g_xn(4096,512) @ in_proj_w(2048,512)^T -> g_ul (1024 CTAs)
    gemm_tc<128, 64, 0, 0><<<dim3(2048 / 64, BL_ / 128, 1), 256>>>(
        512, 0, 1, /*A*/0, 0, 512, in_proj_w, in_proj_w, 512,
        /*C*/1, 1, 2048, nullptr, nullptr);

    // 3) causal conv + SiLU, fwd + bwd(reversed)
    conv_silu_kernel<<<dim3((BL_ * DIN_) / 256, 2), 256>>>(
        conv_w_fw, conv_b_fw, conv_w_bw, conv_b_bw);

    // 4) x_proj split-K (8 chunks of 128) x 2 branches -> partials (1024 CTAs)
    gemm_tc<64, 64, 0, 1><<<dim3(1, BL_ / 64, 16), 256>>>(
        1024, 128, 8, /*A*/2, 3, 1024, xproj_w_fw, xproj_w_bw, 1024,
        0, 0, 64, nullptr, nullptr);
    reduce_split_kernel<<<(2 * BL_ * 64 / 4) / 256, 256>>>(
        8, BL_ * 64 / 4, /*dst*/4, 5);

    // 5) delta both branches fused: softplus(dt(4096,32) @ dt_w^T + b) (1024 CTAs)
    gemm_tc<128, 64, 1, 0><<<dim3(1024 / 64, BL_ / 128, 2), 256>>>(
        32, 0, 1, /*A*/4, 5, 64, dt_w_fw, dt_w_bw, 32,
        /*C*/6, 7, 1024, dt_b_fw, dt_b_bw);

    // 6) selective scans (both branches concurrent via grid.z)
    scan_kernel<<<dim3(DIN_ / 32, B_, 2), 512>>>(A_log_fw, A_log_bw);

    // 7) combine with gate g = silu(z)
    combine_kernel<<<(BL_ * DIN_) / 256, 256>>>(D_fw, D_bw);

    // 8) out_proj split-K=2: g_yc(4096,1024) @ out_proj_w(512,1024)^T (1024 CTAs)
    gemm_tc<64, 64, 0, 1><<<dim3(512 / 64, BL_ / 64, 2), 256>>>(
        1024, 512, 2, /*A*/8, 8, 1024, out_proj_w, out_proj_w, 1024,
        0, 0, 512, nullptr, nullptr);
    reduce_split_kernel<<<(BL_ * 512 / 4) / 256, 256>>>(
        2, BL_ * 512 / 4, /*dst*/9, 9);

    // 9) LN2(residual + out_pre) -> d_out
    ln_kernel<<<BL_, 128>>>(x, ln2_w, ln2_b, out, 1);
}

// round 7
// speedup vs baseline: 2.1529x; 1.2226x over previous
#include <cuda_runtime.h>
#include <cstdint>
#include <cstddef>

// ---------------- problem constants ----------------
constexpr int B_   = 2;
constexpr int L_   = 2048;
constexpr int DIM_ = 512;
constexpr int DIN_ = 1024;
constexpr int DST_ = 16;
constexpr int BL_  = B_ * L_;          // 4096 rows
#define LOG2E_F 1.4426950408889634f

// ---------------- scratch (static device globals; no allocation) ----------------
__device__ float g_xn    [(size_t)BL_ * DIM_];        // LN1 output
__device__ float g_ul    [(size_t)BL_ * 2 * DIN_];    // in_proj output [u | z]
__device__ float g_ucf   [(size_t)BL_ * DIN_];        // conv+silu fwd
__device__ float g_ucb   [(size_t)BL_ * DIN_];        // conv+silu bwd (reversed time)
__device__ float g_xdblf [(size_t)BL_ * 64];          // x_proj fwd [dt|B|C]
__device__ float g_xdblb [(size_t)BL_ * 64];
__device__ float g_deltaf[(size_t)BL_ * DIN_];
__device__ float g_deltab[(size_t)BL_ * DIN_];
__device__ float g_ysf   [(size_t)BL_ * DIN_];        // scan output fwd
__device__ float g_ysb   [(size_t)BL_ * DIN_];        // scan output bwd (reversed time)
__device__ float g_yc    [(size_t)BL_ * DIN_];        // combined y
__device__ float g_part  [(size_t)4194304];           // split-K partials (16 MB)

__device__ __forceinline__ float* get_buf(int id) {
    switch (id) {
        case 0: return g_xn;
        case 1: return g_ul;
        case 2: return g_ucf;
        case 3: return g_ucb;
        case 4: return g_xdblf;
        case 5: return g_xdblb;
        case 6: return g_deltaf;
        case 7: return g_deltab;
        default: return g_yc;
    }
}

// ---------------- small math helpers ----------------
__device__ __forceinline__ float ex2f_(float x) {
    float y; asm("ex2.approx.ftz.f32 %0, %1;" : "=f"(y) : "f"(x)); return y;
}
__device__ __forceinline__ float silu_f(float x) {
    return x / (1.0f + ex2f_(-LOG2E_F * x));
}
__device__ __forceinline__ float softplus_f(float x) {
    return fmaxf(x, 0.0f) + log1pf(__expf(-fabsf(x)));
}
__device__ __forceinline__ void mma_tf32(float c[4], const unsigned a[4],
                                         unsigned b0, unsigned b1) {
    asm volatile(
        "mma.sync.aligned.m16n8k8.row.col.f32.tf32.tf32.f32 "
        "{%0,%1,%2,%3}, {%4,%5,%6,%7}, {%8,%9}, {%0,%1,%2,%3};"
        : "+f"(c[0]), "+f"(c[1]), "+f"(c[2]), "+f"(c[3])
        : "r"(a[0]), "r"(a[1]), "r"(a[2]), "r"(a[3]), "r"(b0), "r"(b1));
}
__device__ __forceinline__ void cp16(uint32_t smem_dst, const void* gsrc) {
    asm volatile("cp.async.cg.shared.global [%0], [%1], 16;"
                 :: "r"(smem_dst), "l"(gsrc));
}
#define CP_COMMIT()  asm volatile("cp.async.commit_group;")
#define CP_WAIT0()   asm volatile("cp.async.wait_group 0;")

// ---------------- LayerNorm ----------------------------------------------------
// mode 0: LN1  x -> g_xn
// mode 1: LN2  (x + part0 + part1) -> out   (out_proj split-K reduce fused in)
__global__ __launch_bounds__(128) void ln_kernel(
    const float* __restrict__ x, const float* __restrict__ w,
    const float* __restrict__ bvec, float* __restrict__ outp, int mode)
{
    __shared__ float red[8];
    const int row = blockIdx.x;
    const int tid = threadIdx.x;     // 128 threads, 4 floats each (DIM=512)

    float4 v = reinterpret_cast<const float4*>(x + (size_t)row * DIM_)[tid];
    if (mode) {
        float4 r0 = reinterpret_cast<const float4*>(g_part + (size_t)row * DIM_)[tid];
        float4 r1 = reinterpret_cast<const float4*>(
                        g_part + (size_t)BL_ * DIM_ + (size_t)row * DIM_)[tid];
        v.x += r0.x + r1.x; v.y += r0.y + r1.y;
        v.z += r0.z + r1.z; v.w += r0.w + r1.w;
    }
    float s  = v.x + v.y + v.z + v.w;
    float ss = v.x*v.x + v.y*v.y + v.z*v.z + v.w*v.w;
    #pragma unroll
    for (int o = 16; o; o >>= 1) {
        s  += __shfl_xor_sync(0xffffffffu, s,  o);
        ss += __shfl_xor_sync(0xffffffffu, ss, o);
    }
    if ((tid & 31) == 0) { red[tid >> 5] = s; red[4 + (tid >> 5)] = ss; }
    __syncthreads();
    s  = red[0] + red[1] + red[2] + red[3];
    ss = red[4] + red[5] + red[6] + red[7];
    const float mean = s * (1.0f / DIM_);
    const float var  = ss * (1.0f / DIM_) - mean * mean;
    const float inv  = rsqrtf(var + 1e-5f);

    float4 wv = reinterpret_cast<const float4*>(w)[tid];
    float4 bv = reinterpret_cast<const float4*>(bvec)[tid];
    float4 o4;
    o4.x = (v.x - mean) * inv * wv.x + bv.x;
    o4.y = (v.y - mean) * inv * wv.y + bv.y;
    o4.z = (v.z - mean) * inv * wv.z + bv.z;
    o4.w = (v.w - mean) * inv * wv.w + bv.w;
    float* dst = mode ? outp : g_xn;
    reinterpret_cast<float4*>(dst + (size_t)row * DIM_)[tid] = o4;
}

// ---------------- tf32 tensor-core GEMM with cp.async double buffer -------------
// C(M,N) = A(M,K) @ W(N,K)^T. 256 threads, 8 warps.
// MODE 0: blockIdx.z selects branch {aid0/W0/cid0/b0, aid1/...}, full K.
// MODE 1: split-K. blockIdx.z = branch*nsplit + ks; K range [ks*kchunk, ...);
//         output partial to g_part[z*Mtot*ldc + row*ldc + col].
// Raw fp32 is staged to smem; tf32 MMA truncates mantissa in hardware.
// EPI: 0 = none, 1 = +bias[n] then softplus.
template <int BM, int BN, int EPI, int MODE>
__global__ __launch_bounds__(256) void gemm_tc(
    int Kd, int kchunk, int nsplit,
    int aid0, int aid1, int lda,
    const float* __restrict__ W0, const float* __restrict__ W1, int ldw,
    int cid0, int cid1, int ldc,
    const float* __restrict__ b0p, const float* __restrict__ b1p)
{
    constexpr int WARPS_M = BM / 32;
    constexpr int WARPS_N = 8 / WARPS_M;
    constexpr int WTN = BN / WARPS_N;          // warp tile n
    constexpr int NF  = WTN / 8;               // n-frags per warp
    constexpr int AF4 = BM / 64;               // 16B copies/thread for A tile
    constexpr int WF4 = BN / 64;
    constexpr int SST = 20;                    // smem row stride (floats)

    __shared__ __align__(16) float sA[2][BM * SST];
    __shared__ __align__(16) float sW[2][BN * SST];

    const int z = blockIdx.z;
    int br, k_begin, k_end;
    if (MODE == 1) { br = z / nsplit; const int ks = z - br * nsplit;
                     k_begin = ks * kchunk; k_end = k_begin + kchunk; }
    else           { br = z; k_begin = 0; k_end = Kd; }

    const float* __restrict__ A    = get_buf(br ? aid1 : aid0);
    const float* __restrict__ W    = br ? W1 : W0;
    const float* __restrict__ bias = br ? b1p : b0p;

    const int tid  = threadIdx.x;
    const int lane = tid & 31;
    const int warp = tid >> 5;
    const int g    = lane >> 2;
    const int tig  = lane & 3;
    const int wm   = warp % WARPS_M;
    const int wn   = warp / WARPS_M;
    const int m0   = blockIdx.y * BM;
    const int n0   = blockIdx.x * BN;
    const int Mtot = gridDim.y * BM;

    const uint32_t sAb = (uint32_t)__cvta_generic_to_shared(&sA[0][0]);
    const uint32_t sWb = (uint32_t)__cvta_generic_to_shared(&sW[0][0]);

    float acc[2][NF][4];
    #pragma unroll
    for (int i = 0; i < 2; i++)
        #pragma unroll
        for (int j = 0; j < NF; j++)
            #pragma unroll
            for (int q = 0; q < 4; q++) acc[i][j][q] = 0.0f;

    auto ldTileAsync = [&](int k0, int bufi) {
        #pragma unroll
        for (int i = 0; i < AF4; i++) {
            const int idx = tid + i * 256;
            const int r = idx >> 2, kk = (idx & 3) * 4;
            cp16(sAb + (uint32_t)(bufi * BM * SST + r * SST + kk) * 4,
                 A + (size_t)(m0 + r) * lda + k0 + kk);
        }
        #pragma unroll
        for (int i = 0; i < WF4; i++) {
            const int idx = tid + i * 256;
            const int r = idx >> 2, kk = (idx & 3) * 4;
            cp16(sWb + (uint32_t)(bufi * BN * SST + r * SST + kk) * 4,
                 W + (size_t)(n0 + r) * ldw + k0 + kk);
        }
    };
    auto compute = [&](int bufi) {
        const unsigned* uA = reinterpret_cast<const unsigned*>(&sA[bufi][0]);
        const unsigned* uW = reinterpret_cast<const unsigned*>(&sW[bufi][0]);
        #pragma unroll
        for (int ks = 0; ks < 16; ks += 8) {
            unsigned af[2][4];
            #pragma unroll
            for (int im = 0; im < 2; im++) {
                const int base = (wm * 32 + im * 16 + g) * SST + ks;
                af[im][0] = uA[base + tig];
                af[im][1] = uA[base + 8 * SST + tig];
                af[im][2] = uA[base + 4 + tig];
                af[im][3] = uA[base + 8 * SST + 4 + tig];
            }
            #pragma unroll
            for (int in = 0; in < NF; in++) {
                const int nb = (wn * WTN + in * 8 + g) * SST + ks;
                const unsigned bf0 = uW[nb + tig];
                const unsigned bf1 = uW[nb + 4 + tig];
                #pragma unroll
                for (int im = 0; im < 2; im++)
                    mma_tf32(acc[im][in], af[im], bf0, bf1);
            }
        }
    };

    // pipeline: copy(k+1) overlaps MMA(k)
    ldTileAsync(k_begin, 0);
    CP_COMMIT();
    int buf = 0;
    for (int k0 = k_begin; k0 < k_end; k0 += 16) {
        CP_WAIT0();
        __syncthreads();
        if (k0 + 16 < k_end) { ldTileAsync(k0 + 16, buf ^ 1); CP_COMMIT(); }
        compute(buf);
        buf ^= 1;
    }

    // epilogue
    float* __restrict__ Cp;
    if (MODE == 1) Cp = g_part + (size_t)z * (size_t)Mtot * ldc;
    else           Cp = get_buf(br ? cid1 : cid0);

    #pragma unroll
    for (int im = 0; im < 2; im++) {
        #pragma unroll
        for (int in = 0; in < NF; in++) {
            const int row = m0 + wm * 32 + im * 16 + g;
            const int col = n0 + wn * WTN + in * 8 + 2 * tig;
            float v0 = acc[im][in][0], v1 = acc[im][in][1];
            float v2 = acc[im][in][2], v3 = acc[im][in][3];
            if (EPI == 1) {
                const float bc0 = bias[col], bc1 = bias[col + 1];
                v0 = softplus_f(v0 + bc0); v1 = softplus_f(v1 + bc1);
                v2 = softplus_f(v2 + bc0); v3 = softplus_f(v3 + bc1);
            }
            *reinterpret_cast<float2*>(&Cp[(size_t)row * ldc + col])       = make_float2(v0, v1);
            *reinterpret_cast<float2*>(&Cp[(size_t)(row + 8) * ldc + col]) = make_float2(v2, v3);
        }
    }
}

// ---------------- split-K reduce (x_proj): dst[br] = sum_s part[br*nsplit+s] ----
__global__ __launch_bounds__(256) void reduce_split_kernel(
    int nsplit, int elems4, int dst0, int dst1)
{
    const int i = blockIdx.x * 256 + threadIdx.x;
    const int br = i / elems4;
    const int off = i - br * elems4;
    const float4* p = reinterpret_cast<const float4*>(g_part)
                    + (size_t)(br * nsplit) * elems4 + off;
    float4 a = p[0];
    for (int s = 1; s < nsplit; s++) {
        const float4 v = p[(size_t)s * elems4];
        a.x += v.x; a.y += v.y; a.z += v.z; a.w += v.w;
    }
    reinterpret_cast<float4*>(get_buf(br ? dst1 : dst0))[off] = a;
}

// ---------------- depthwise causal conv (K=4) + SiLU, both branches in one ------
__global__ __launch_bounds__(256) void conv_silu_kernel(
    const float* __restrict__ wf, const float* __restrict__ biasf,
    const float* __restrict__ wb, const float* __restrict__ biasb)
{
    const int i  = blockIdx.x * 256 + threadIdx.x;     // over BL*DIN
    const int d  = i & (DIN_ - 1);
    const int t  = (i >> 10) & (L_ - 1);
    const int b  = i >> 21;

    float af = biasf[d];
    float ab = biasb[d];
    #pragma unroll
    for (int k = 0; k < 4; k++) {
        const int s = t - 3 + k;
        if (s >= 0) {
            af += wf[d * 4 + k] * g_ul[((size_t)(b * L_ + s) << 11) + d];
            ab += wb[d * 4 + k] * g_ul[((size_t)(b * L_ + (L_ - 1 - s)) << 11) + d];
        }
    }
    const size_t oi = ((size_t)(b * L_ + t) << 10) + d;
    g_ucf[oi] = silu_f(af);
    g_ucb[oi] = silu_f(ab);
}

// ---------------- selective scan (cp.async double-buffered tiles) ---------------
// thread = (state n, local channel dl); block = 32 channels x 16 states = 512 thr
// grid = (DIN/32, B, 2 branches). h = exp(delta*A)*h + delta*u*B; y = <h,C>
__global__ __launch_bounds__(512) void scan_kernel(
    const float* __restrict__ AlogF, const float* __restrict__ AlogB)
{
    const int br = blockIdx.z;
    const int b  = blockIdx.y;
    const int d0 = blockIdx.x * 32;
    const int tid = threadIdx.x;
    const int n  = tid & 15;
    const int dl = tid >> 4;
    const int d  = d0 + dl;

    const float* __restrict__ delta = br ? g_deltab : g_deltaf;
    const float* __restrict__ xdbl  = br ? g_xdblb  : g_xdblf;
    const float* __restrict__ uc    = br ? g_ucb    : g_ucf;
    const float* __restrict__ Alog  = br ? AlogB    : AlogF;
    float* __restrict__ ys          = br ? g_ysb    : g_ysf;

    // A = -exp(A_log); pre-fold log2(e) so the step uses EX2 directly
    const float AL2 = -__expf(Alog[d * DST_ + n]) * LOG2E_F;

    __shared__ __align__(16) float sdl[2][64 * 32];
    __shared__ __align__(16) float suc[2][64 * 32];
    __shared__ __align__(16) float sbc[2][64 * 32];
    __shared__ float sy[64][33];

    const uint32_t sdl_b = (uint32_t)__cvta_generic_to_shared(&sdl[0][0]);
    const uint32_t suc_b = (uint32_t)__cvta_generic_to_shared(&suc[0][0]);
    const uint32_t sbc_b = (uint32_t)__cvta_generic_to_shared(&sbc[0][0]);

    // one 16B copy per array per thread per tile (512 threads cover 64x32)
    const int srow = tid >> 3;
    const int sch  = (tid & 7) * 4;
    auto stage = [&](int t0, int bufi) {
        const size_t gr = ((size_t)(b * L_ + t0 + srow) << 10) + d0 + sch;
        const uint32_t so = (uint32_t)(bufi * 2048 + srow * 32 + sch) * 4;
        cp16(sdl_b + so, delta + gr);
        cp16(suc_b + so, uc + gr);
        cp16(sbc_b + so, xdbl + (((size_t)(b * L_ + t0 + srow)) << 6) + 32 + sch);
    };

    stage(0, 0);
    CP_COMMIT();
    float h = 0.0f;
    int buf = 0;

    for (int t0 = 0; t0 < L_; t0 += 64) {
        CP_WAIT0();
        __syncthreads();
        if (t0 + 64 < L_) { stage(t0 + 64, buf ^ 1); CP_COMMIT(); }

        #pragma unroll 8
        for (int tt = 0; tt < 64; tt++) {
            const float dv = sdl[buf][tt * 32 + dl];
            const float uv = suc[buf][tt * 32 + dl];
            const float bb = sbc[buf][tt * 32 + n];
            const float cc = sbc[buf][tt * 32 + 16 + n];
            const float e  = ex2f_(dv * AL2);
            h = fmaf(e, h, dv * uv * bb);
            float p = h * cc;
            p += __shfl_xor_sync(0xffffffffu, p, 1);
            p += __shfl_xor_sync(0xffffffffu, p, 2);
            p += __shfl_xor_sync(0xffffffffu, p, 4);
            p += __shfl_xor_sync(0xffffffffu, p, 8);
            if (n == 0) sy[tt][dl] = p;
        }
        __syncthreads();

        #pragma unroll
        for (int i = tid; i < 64 * 32; i += 512) {
            const int tt = i >> 5, c = i & 31;
            ys[((size_t)(b * L_ + t0 + tt) << 10) + d0 + c] = sy[tt][c];
        }
        buf ^= 1;
        // next iteration's top sync orders sy reads before overwrite
    }
}

// ---------------- combine: yc = g*(ys_f + uc_f*D_f + rev(ys_b + uc_b*D_b)) ------
__global__ __launch_bounds__(256) void combine_kernel(
    const float* __restrict__ Df, const float* __restrict__ Db)
{
    const int i = blockIdx.x * 256 + threadIdx.x;      // over BL*DIN
    const int d = i & (DIN_ - 1);
    const int t = (i >> 10) & (L_ - 1);
    const int b = i >> 21;

    const float z  = g_ul[((size_t)(b * L_ + t) << 11) + DIN_ + d];
    const float gg = silu_f(z);
    const size_t fi = (size_t)i;
    const size_t bi = ((size_t)(b * L_ + (L_ - 1 - t)) << 10) + d;
    const float yf = g_ysf[fi] + g_ucf[fi] * Df[d];
    const float yr = g_ysb[bi] + g_ucb[bi] * Db[d];
    g_yc[fi] = gg * (yf + yr);
}

// ---------------- launch ----------------
extern "C" void kernel_launch(void* const* d_in, const int* in_sizes, int n_in,
                              void* d_out, int out_size)
{
    const float* x          = (const float*)d_in[0];
    const float* ln1_w      = (const float*)d_in[1];
    const float* ln1_b      = (const float*)d_in[2];
    const float* ln2_w      = (const float*)d_in[3];
    const float* ln2_b      = (const float*)d_in[4];
    const float* in_proj_w  = (const float*)d_in[5];
    const float* conv_w_fw  = (const float*)d_in[6];
    const float* conv_b_fw  = (const float*)d_in[7];
    const float* xproj_w_fw = (const float*)d_in[8];
    const float* dt_w_fw    = (const float*)d_in[9];
    const float* dt_b_fw    = (const float*)d_in[10];
    const float* A_log_fw   = (const float*)d_in[11];
    const float* D_fw       = (const float*)d_in[12];
    const float* conv_w_bw  = (const float*)d_in[13];
    const float* conv_b_bw  = (const float*)d_in[14];
    const float* xproj_w_bw = (const float*)d_in[15];
    const float* dt_w_bw    = (const float*)d_in[16];
    const float* dt_b_bw    = (const float*)d_in[17];
    const float* A_log_bw   = (const float*)d_in[18];
    const float* D_bw       = (const float*)d_in[19];
    const float* out_proj_w = (const float*)d_in[20];
    float* out = (float*)d_out;

    // 1) LN1: x -> g_xn
    ln_kernel<<<BL_, 128>>>(x, ln1_w, ln1_b, nullptr, 0);

    // 2) in_proj: g_xn(4096,512) @ in_proj_w(2048,512)^T -> g_ul (512 CTAs, 128x128)
    gemm_tc<128, 128, 0, 0><<<dim3(2048 / 128, BL_ / 128, 1), 256>>>(
        512, 0, 1, /*A*/0, 0, 512, in_proj_w, in_proj_w, 512,
        /*C*/1, 1, 2048, nullptr, nullptr);

    // 3) causal conv + SiLU, fwd + bwd fused in one kernel
    conv_silu_kernel<<<(BL_ * DIN_) / 256, 256>>>(
        conv_w_fw, conv_b_fw, conv_w_bw, conv_b_bw);

    // 4) x_proj split-K (8 chunks of 128) x 2 branches -> partials (512 CTAs)
    gemm_tc<128, 64, 0, 1><<<dim3(1, BL_ / 128, 16), 256>>>(
        1024, 128, 8, /*A*/2, 3, 1024, xproj_w_fw, xproj_w_bw, 1024,
        0, 0, 64, nullptr, nullptr);
    reduce_split_kernel<<<(2 * BL_ * 64 / 4) / 256, 256>>>(
        8, BL_ * 64 / 4, /*dst*/4, 5);

    // 5) delta both branches fused: softplus(dt(4096,32) @ dt_w^T + b) (1024 CTAs)
    gemm_tc<128, 64, 1, 0><<<dim3(1024 / 64, BL_ / 128, 2), 256>>>(
        32, 0, 1, /*A*/4, 5, 64, dt_w_fw, dt_w_bw, 32,
        /*C*/6, 7, 1024, dt_b_fw, dt_b_bw);

    // 6) selective scans (both branches concurrent via grid.z), double-buffered
    scan_kernel<<<dim3(DIN_ / 32, B_, 2), 512>>>(A_log_fw, A_log_bw);

    // 7) combine with gate g = silu(z)
    combine_kernel<<<(BL_ * DIN_) / 256, 256>>>(D_fw, D_bw);

    // 8) out_proj split-K=2: g_yc(4096,1024) @ out_proj_w(512,1024)^T (512 CTAs)
    gemm_tc<128, 64, 0, 1><<<dim3(512 / 64, BL_ / 128, 2), 256>>>(
        1024, 512, 2, /*A*/8, 8, 1024, out_proj_w, out_proj_w, 1024,
        0, 0, 512, nullptr, nullptr);

    // 9) LN2(residual + partial0 + partial1) -> d_out  (reduce fused)
    ln_kernel<<<BL_, 128>>>(x, ln2_w, ln2_b, out, 1);
}

// round 8
// speedup vs baseline: 2.2121x; 1.0275x over previous
#include <cuda_runtime.h>
#include <cstdint>
#include <cstddef>

// ---------------- problem constants ----------------
constexpr int B_   = 2;
constexpr int L_   = 2048;
constexpr int DIM_ = 512;
constexpr int DIN_ = 1024;
constexpr int DST_ = 16;
constexpr int BL_  = B_ * L_;          // 4096 rows
constexpr int NCH_ = 8;                // scan chunks
constexpr int CH_  = L_ / NCH_;        // 256 steps per chunk
#define LOG2E_F 1.4426950408889634f

// ---------------- scratch (static device globals; no allocation) ----------------
__device__ float g_xn    [(size_t)BL_ * DIM_];        // LN1 output
__device__ float g_ul    [(size_t)BL_ * 2 * DIN_];    // in_proj output [u | z]
__device__ float g_ucf   [(size_t)BL_ * DIN_];        // conv+silu fwd
__device__ float g_ucb   [(size_t)BL_ * DIN_];        // conv+silu bwd (reversed time)
__device__ float g_xdblf [(size_t)BL_ * 64];          // x_proj fwd [dt|B|C]
__device__ float g_xdblb [(size_t)BL_ * 64];
__device__ float g_deltaf[(size_t)BL_ * DIN_];
__device__ float g_deltab[(size_t)BL_ * DIN_];
__device__ float g_ysf   [(size_t)BL_ * DIN_];        // scan output fwd
__device__ float g_ysb   [(size_t)BL_ * DIN_];        // scan output bwd (reversed time)
__device__ float g_yc    [(size_t)BL_ * DIN_];        // combined y
__device__ float g_part  [(size_t)4194304];           // split-K partials / scan states

// scan state slabs inside g_part (free between x_proj reduce and out_proj):
// E (chunk-end states):  [0, 512K)
// P (chunk decay prods): [512K, 1M)
// H (chunk entry states):[1M, 1.5M)
constexpr size_t SC_E = 0;
constexpr size_t SC_P = 524288;
constexpr size_t SC_H = 1048576;
constexpr int SC_PER = DIN_ * DST_;    // 16384 values per (branch,batch,chunk)

__device__ __forceinline__ float* get_buf(int id) {
    switch (id) {
        case 0: return g_xn;
        case 1: return g_ul;
        case 2: return g_ucf;
        case 3: return g_ucb;
        case 4: return g_xdblf;
        case 5: return g_xdblb;
        case 6: return g_deltaf;
        case 7: return g_deltab;
        default: return g_yc;
    }
}

// ---------------- small math helpers ----------------
__device__ __forceinline__ float ex2f_(float x) {
    float y; asm("ex2.approx.ftz.f32 %0, %1;" : "=f"(y) : "f"(x)); return y;
}
__device__ __forceinline__ float silu_f(float x) {
    return x / (1.0f + ex2f_(-LOG2E_F * x));
}
__device__ __forceinline__ float softplus_f(float x) {
    return fmaxf(x, 0.0f) + log1pf(__expf(-fabsf(x)));
}
__device__ __forceinline__ void mma_tf32(float c[4], const unsigned a[4],
                                         unsigned b0, unsigned b1) {
    asm volatile(
        "mma.sync.aligned.m16n8k8.row.col.f32.tf32.tf32.f32 "
        "{%0,%1,%2,%3}, {%4,%5,%6,%7}, {%8,%9}, {%0,%1,%2,%3};"
        : "+f"(c[0]), "+f"(c[1]), "+f"(c[2]), "+f"(c[3])
        : "r"(a[0]), "r"(a[1]), "r"(a[2]), "r"(a[3]), "r"(b0), "r"(b1));
}
__device__ __forceinline__ void cp16(uint32_t smem_dst, const void* gsrc) {
    asm volatile("cp.async.cg.shared.global [%0], [%1], 16;"
                 :: "r"(smem_dst), "l"(gsrc));
}
#define CP_COMMIT()  asm volatile("cp.async.commit_group;")
#define CP_WAIT0()   asm volatile("cp.async.wait_group 0;")

// ---------------- LayerNorm ----------------------------------------------------
// mode 0: LN1  x -> g_xn
// mode 1: LN2  (x + part0 + part1) -> out   (out_proj split-K reduce fused in)
__global__ __launch_bounds__(128) void ln_kernel(
    const float* __restrict__ x, const float* __restrict__ w,
    const float* __restrict__ bvec, float* __restrict__ outp, int mode)
{
    __shared__ float red[8];
    const int row = blockIdx.x;
    const int tid = threadIdx.x;     // 128 threads, 4 floats each (DIM=512)

    float4 v = reinterpret_cast<const float4*>(x + (size_t)row * DIM_)[tid];
    if (mode) {
        float4 r0 = reinterpret_cast<const float4*>(g_part + (size_t)row * DIM_)[tid];
        float4 r1 = reinterpret_cast<const float4*>(
                        g_part + (size_t)BL_ * DIM_ + (size_t)row * DIM_)[tid];
        v.x += r0.x + r1.x; v.y += r0.y + r1.y;
        v.z += r0.z + r1.z; v.w += r0.w + r1.w;
    }
    float s  = v.x + v.y + v.z + v.w;
    float ss = v.x*v.x + v.y*v.y + v.z*v.z + v.w*v.w;
    #pragma unroll
    for (int o = 16; o; o >>= 1) {
        s  += __shfl_xor_sync(0xffffffffu, s,  o);
        ss += __shfl_xor_sync(0xffffffffu, ss, o);
    }
    if ((tid & 31) == 0) { red[tid >> 5] = s; red[4 + (tid >> 5)] = ss; }
    __syncthreads();
    s  = red[0] + red[1] + red[2] + red[3];
    ss = red[4] + red[5] + red[6] + red[7];
    const float mean = s * (1.0f / DIM_);
    const float var  = ss * (1.0f / DIM_) - mean * mean;
    const float inv  = rsqrtf(var + 1e-5f);

    float4 wv = reinterpret_cast<const float4*>(w)[tid];
    float4 bv = reinterpret_cast<const float4*>(bvec)[tid];
    float4 o4;
    o4.x = (v.x - mean) * inv * wv.x + bv.x;
    o4.y = (v.y - mean) * inv * wv.y + bv.y;
    o4.z = (v.z - mean) * inv * wv.z + bv.z;
    o4.w = (v.w - mean) * inv * wv.w + bv.w;
    float* dst = mode ? outp : g_xn;
    reinterpret_cast<float4*>(dst + (size_t)row * DIM_)[tid] = o4;
}

// ---------------- tf32 tensor-core GEMM with cp.async double buffer -------------
// C(M,N) = A(M,K) @ W(N,K)^T. 256 threads, 8 warps.
// MODE 0: blockIdx.z selects branch {aid0/W0/cid0/b0, aid1/...}, full K.
// MODE 1: split-K. blockIdx.z = branch*nsplit + ks; K range [ks*kchunk, ...);
//         output partial to g_part[z*Mtot*ldc + row*ldc + col].
// Raw fp32 is staged to smem; tf32 MMA truncates mantissa in hardware.
// EPI: 0 = none, 1 = +bias[n] then softplus.
template <int BM, int BN, int EPI, int MODE>
__global__ __launch_bounds__(256) void gemm_tc(
    int Kd, int kchunk, int nsplit,
    int aid0, int aid1, int lda,
    const float* __restrict__ W0, const float* __restrict__ W1, int ldw,
    int cid0, int cid1, int ldc,
    const float* __restrict__ b0p, const float* __restrict__ b1p)
{
    constexpr int WARPS_M = BM / 32;
    constexpr int WARPS_N = 8 / WARPS_M;
    constexpr int WTN = BN / WARPS_N;          // warp tile n
    constexpr int NF  = WTN / 8;               // n-frags per warp
    constexpr int AF4 = BM / 64;               // 16B copies/thread for A tile
    constexpr int WF4 = BN / 64;
    constexpr int SST = 20;                    // smem row stride (floats)

    __shared__ __align__(16) float sA[2][BM * SST];
    __shared__ __align__(16) float sW[2][BN * SST];

    const int z = blockIdx.z;
    int br, k_begin, k_end;
    if (MODE == 1) { br = z / nsplit; const int ks = z - br * nsplit;
                     k_begin = ks * kchunk; k_end = k_begin + kchunk; }
    else           { br = z; k_begin = 0; k_end = Kd; }

    const float* __restrict__ A    = get_buf(br ? aid1 : aid0);
    const float* __restrict__ W    = br ? W1 : W0;
    const float* __restrict__ bias = br ? b1p : b0p;

    const int tid  = threadIdx.x;
    const int lane = tid & 31;
    const int warp = tid >> 5;
    const int g    = lane >> 2;
    const int tig  = lane & 3;
    const int wm   = warp % WARPS_M;
    const int wn   = warp / WARPS_M;
    const int m0   = blockIdx.y * BM;
    const int n0   = blockIdx.x * BN;
    const int Mtot = gridDim.y * BM;

    const uint32_t sAb = (uint32_t)__cvta_generic_to_shared(&sA[0][0]);
    const uint32_t sWb = (uint32_t)__cvta_generic_to_shared(&sW[0][0]);

    float acc[2][NF][4];
    #pragma unroll
    for (int i = 0; i < 2; i++)
        #pragma unroll
        for (int j = 0; j < NF; j++)
            #pragma unroll
            for (int q = 0; q < 4; q++) acc[i][j][q] = 0.0f;

    auto ldTileAsync = [&](int k0, int bufi) {
        #pragma unroll
        for (int i = 0; i < AF4; i++) {
            const int idx = tid + i * 256;
            const int r = idx >> 2, kk = (idx & 3) * 4;
            cp16(sAb + (uint32_t)(bufi * BM * SST + r * SST + kk) * 4,
                 A + (size_t)(m0 + r) * lda + k0 + kk);
        }
        #pragma unroll
        for (int i = 0; i < WF4; i++) {
            const int idx = tid + i * 256;
            const int r = idx >> 2, kk = (idx & 3) * 4;
            cp16(sWb + (uint32_t)(bufi * BN * SST + r * SST + kk) * 4,
                 W + (size_t)(n0 + r) * ldw + k0 + kk);
        }
    };
    auto compute = [&](int bufi) {
        const unsigned* uA = reinterpret_cast<const unsigned*>(&sA[bufi][0]);
        const unsigned* uW = reinterpret_cast<const unsigned*>(&sW[bufi][0]);
        #pragma unroll
        for (int ks = 0; ks < 16; ks += 8) {
            unsigned af[2][4];
            #pragma unroll
            for (int im = 0; im < 2; im++) {
                const int base = (wm * 32 + im * 16 + g) * SST + ks;
                af[im][0] = uA[base + tig];
                af[im][1] = uA[base + 8 * SST + tig];
                af[im][2] = uA[base + 4 + tig];
                af[im][3] = uA[base + 8 * SST + 4 + tig];
            }
            #pragma unroll
            for (int in = 0; in < NF; in++) {
                const int nb = (wn * WTN + in * 8 + g) * SST + ks;
                const unsigned bf0 = uW[nb + tig];
                const unsigned bf1 = uW[nb + 4 + tig];
                #pragma unroll
                for (int im = 0; im < 2; im++)
                    mma_tf32(acc[im][in], af[im], bf0, bf1);
            }
        }
    };

    // pipeline: copy(k+1) overlaps MMA(k)
    ldTileAsync(k_begin, 0);
    CP_COMMIT();
    int buf = 0;
    for (int k0 = k_begin; k0 < k_end; k0 += 16) {
        CP_WAIT0();
        __syncthreads();
        if (k0 + 16 < k_end) { ldTileAsync(k0 + 16, buf ^ 1); CP_COMMIT(); }
        compute(buf);
        buf ^= 1;
    }

    // epilogue
    float* __restrict__ Cp;
    if (MODE == 1) Cp = g_part + (size_t)z * (size_t)Mtot * ldc;
    else           Cp = get_buf(br ? cid1 : cid0);

    #pragma unroll
    for (int im = 0; im < 2; im++) {
        #pragma unroll
        for (int in = 0; in < NF; in++) {
            const int row = m0 + wm * 32 + im * 16 + g;
            const int col = n0 + wn * WTN + in * 8 + 2 * tig;
            float v0 = acc[im][in][0], v1 = acc[im][in][1];
            float v2 = acc[im][in][2], v3 = acc[im][in][3];
            if (EPI == 1) {
                const float bc0 = bias[col], bc1 = bias[col + 1];
                v0 = softplus_f(v0 + bc0); v1 = softplus_f(v1 + bc1);
                v2 = softplus_f(v2 + bc0); v3 = softplus_f(v3 + bc1);
            }
            *reinterpret_cast<float2*>(&Cp[(size_t)row * ldc + col])       = make_float2(v0, v1);
            *reinterpret_cast<float2*>(&Cp[(size_t)(row + 8) * ldc + col]) = make_float2(v2, v3);
        }
    }
}

// ---------------- split-K reduce (x_proj): dst[br] = sum_s part[br*nsplit+s] ----
__global__ __launch_bounds__(256) void reduce_split_kernel(
    int nsplit, int elems4, int dst0, int dst1)
{
    const int i = blockIdx.x * 256 + threadIdx.x;
    const int br = i / elems4;
    const int off = i - br * elems4;
    const float4* p = reinterpret_cast<const float4*>(g_part)
                    + (size_t)(br * nsplit) * elems4 + off;
    float4 a = p[0];
    for (int s = 1; s < nsplit; s++) {
        const float4 v = p[(size_t)s * elems4];
        a.x += v.x; a.y += v.y; a.z += v.z; a.w += v.w;
    }
    reinterpret_cast<float4*>(get_buf(br ? dst1 : dst0))[off] = a;
}

// ---------------- depthwise causal conv (K=4) + SiLU, both branches in one ------
__global__ __launch_bounds__(256) void conv_silu_kernel(
    const float* __restrict__ wf, const float* __restrict__ biasf,
    const float* __restrict__ wb, const float* __restrict__ biasb)
{
    const int i  = blockIdx.x * 256 + threadIdx.x;     // over BL*DIN
    const int d  = i & (DIN_ - 1);
    const int t  = (i >> 10) & (L_ - 1);
    const int b  = i >> 21;

    float af = biasf[d];
    float ab = biasb[d];
    #pragma unroll
    for (int k = 0; k < 4; k++) {
        const int s = t - 3 + k;
        if (s >= 0) {
            af += wf[d * 4 + k] * g_ul[((size_t)(b * L_ + s) << 11) + d];
            ab += wb[d * 4 + k] * g_ul[((size_t)(b * L_ + (L_ - 1 - s)) << 11) + d];
        }
    }
    const size_t oi = ((size_t)(b * L_ + t) << 10) + d;
    g_ucf[oi] = silu_f(af);
    g_ucb[oi] = silu_f(ab);
}

// ---------------- chunked selective scan ----------------------------------------
// Linear recurrence h_t = a_t h_{t-1} + b_t split into NCH chunks of CH steps.
// PASS==1: from h=0, compute chunk-end state E and decay product P (no y).
// PASS==2: from stitched entry state H, recompute chunk and emit y.
// grid (DIN/32, B*NCH, 2 branches), block 512 = 32 channels x 16 states.
template <int PASS>
__global__ __launch_bounds__(512) void scan_chunk_kernel(
    const float* __restrict__ AlogF, const float* __restrict__ AlogB)
{
    const int br = blockIdx.z;
    const int b  = blockIdx.y / NCH_;
    const int ch = blockIdx.y % NCH_;
    const int d0 = blockIdx.x * 32;
    const int tid = threadIdx.x;
    const int n  = tid & 15;
    const int dl = tid >> 4;
    const int d  = d0 + dl;
    const int tbase = ch * CH_;
    const int grp = br * B_ + b;
    const size_t sidx = (size_t)(grp * NCH_ + ch) * SC_PER + d0 * DST_ + tid;

    const float* __restrict__ delta = br ? g_deltab : g_deltaf;
    const float* __restrict__ xdbl  = br ? g_xdblb  : g_xdblf;
    const float* __restrict__ uc    = br ? g_ucb    : g_ucf;
    const float* __restrict__ Alog  = br ? AlogB    : AlogF;
    float* __restrict__ ys          = br ? g_ysb    : g_ysf;

    // A = -exp(A_log); pre-fold log2(e) so the step uses EX2 directly
    const float AL2 = -__expf(Alog[d * DST_ + n]) * LOG2E_F;

    __shared__ __align__(16) float sdl[2][64 * 32];
    __shared__ __align__(16) float suc[2][64 * 32];
    __shared__ __align__(16) float sbc[2][64 * 32];
    __shared__ float sy[64][33];

    const uint32_t sdl_b = (uint32_t)__cvta_generic_to_shared(&sdl[0][0]);
    const uint32_t suc_b = (uint32_t)__cvta_generic_to_shared(&suc[0][0]);
    const uint32_t sbc_b = (uint32_t)__cvta_generic_to_shared(&sbc[0][0]);

    // one 16B copy per array per thread per 64-step tile
    const int srow = tid >> 3;
    const int sch  = (tid & 7) * 4;
    auto stage = [&](int t0, int bufi) {
        const size_t gr = ((size_t)(b * L_ + t0 + srow) << 10) + d0 + sch;
        const uint32_t so = (uint32_t)(bufi * 2048 + srow * 32 + sch) * 4;
        cp16(sdl_b + so, delta + gr);
        cp16(suc_b + so, uc + gr);
        cp16(sbc_b + so, xdbl + (((size_t)(b * L_ + t0 + srow)) << 6) + 32 + sch);
    };

    stage(tbase, 0);
    CP_COMMIT();
    float h    = (PASS == 2) ? g_part[SC_H + sidx] : 0.0f;
    float prod = 1.0f;
    int buf = 0;

    for (int t0 = tbase; t0 < tbase + CH_; t0 += 64) {
        CP_WAIT0();
        __syncthreads();
        if (t0 + 64 < tbase + CH_) { stage(t0 + 64, buf ^ 1); CP_COMMIT(); }

        #pragma unroll 8
        for (int tt = 0; tt < 64; tt++) {
            const float dv = sdl[buf][tt * 32 + dl];
            const float uv = suc[buf][tt * 32 + dl];
            const float bb = sbc[buf][tt * 32 + n];
            const float e  = ex2f_(dv * AL2);
            h = fmaf(e, h, dv * uv * bb);
            if (PASS == 1) {
                prod *= e;
            } else {
                const float cc = sbc[buf][tt * 32 + 16 + n];
                float p = h * cc;
                p += __shfl_xor_sync(0xffffffffu, p, 1);
                p += __shfl_xor_sync(0xffffffffu, p, 2);
                p += __shfl_xor_sync(0xffffffffu, p, 4);
                p += __shfl_xor_sync(0xffffffffu, p, 8);
                if (n == 0) sy[tt][dl] = p;
            }
        }
        if (PASS == 2) {
            __syncthreads();
            #pragma unroll
            for (int i = tid; i < 64 * 32; i += 512) {
                const int tt = i >> 5, c = i & 31;
                ys[((size_t)(b * L_ + t0 + tt) << 10) + d0 + c] = sy[tt][c];
            }
        }
        buf ^= 1;
        // tile boundary: top-of-loop __syncthreads orders smem reuse
    }

    if (PASS == 1) {
        g_part[SC_E + sidx] = h;
        g_part[SC_P + sidx] = prod;
    }
}

// ---------------- stitch: H_c = P_{c-1} H_{c-1} + E_{c-1}, H_0 = 0 ---------------
__global__ __launch_bounds__(256) void scan_stitch_kernel()
{
    const int i = blockIdx.x * 256 + threadIdx.x;      // over 4 * SC_PER = 65536
    const int grp = i / SC_PER;
    const int off = i - grp * SC_PER;
    float run = 0.0f;
    #pragma unroll
    for (int c = 0; c < NCH_; c++) {
        const size_t idx = (size_t)(grp * NCH_ + c) * SC_PER + off;
        g_part[SC_H + idx] = run;
        run = g_part[SC_P + idx] * run + g_part[SC_E + idx];
    }
}

// ---------------- combine: yc = g*(ys_f + uc_f*D_f + rev(ys_b + uc_b*D_b)) ------
__global__ __launch_bounds__(256) void combine_kernel(
    const float* __restrict__ Df, const float* __restrict__ Db)
{
    const int i = blockIdx.x * 256 + threadIdx.x;      // over BL*DIN
    const int d = i & (DIN_ - 1);
    const int t = (i >> 10) & (L_ - 1);
    const int b = i >> 21;

    const float z  = g_ul[((size_t)(b * L_ + t) << 11) + DIN_ + d];
    const float gg = silu_f(z);
    const size_t fi = (size_t)i;
    const size_t bi = ((size_t)(b * L_ + (L_ - 1 - t)) << 10) + d;
    const float yf = g_ysf[fi] + g_ucf[fi] * Df[d];
    const float yr = g_ysb[bi] + g_ucb[bi] * Db[d];
    g_yc[fi] = gg * (yf + yr);
}

// ---------------- launch ----------------
extern "C" void kernel_launch(void* const* d_in, const int* in_sizes, int n_in,
                              void* d_out, int out_size)
{
    const float* x          = (const float*)d_in[0];
    const float* ln1_w      = (const float*)d_in[1];
    const float* ln1_b      = (const float*)d_in[2];
    const float* ln2_w      = (const float*)d_in[3];
    const float* ln2_b      = (const float*)d_in[4];
    const float* in_proj_w  = (const float*)d_in[5];
    const float* conv_w_fw  = (const float*)d_in[6];
    const float* conv_b_fw  = (const float*)d_in[7];
    const float* xproj_w_fw = (const float*)d_in[8];
    const float* dt_w_fw    = (const float*)d_in[9];
    const float* dt_b_fw    = (const float*)d_in[10];
    const float* A_log_fw   = (const float*)d_in[11];
    const float* D_fw       = (const float*)d_in[12];
    const float* conv_w_bw  = (const float*)d_in[13];
    const float* conv_b_bw  = (const float*)d_in[14];
    const float* xproj_w_bw = (const float*)d_in[15];
    const float* dt_w_bw    = (const float*)d_in[16];
    const float* dt_b_bw    = (const float*)d_in[17];
    const float* A_log_bw   = (const float*)d_in[18];
    const float* D_bw       = (const float*)d_in[19];
    const float* out_proj_w = (const float*)d_in[20];
    float* out = (float*)d_out;

    // 1) LN1: x -> g_xn
    ln_kernel<<<BL_, 128>>>(x, ln1_w, ln1_b, nullptr, 0);

    // 2) in_proj: g_xn(4096,512) @ in_proj_w(2048,512)^T -> g_ul (512 CTAs, 128x128)
    gemm_tc<128, 128, 0, 0><<<dim3(2048 / 128, BL_ / 128, 1), 256>>>(
        512, 0, 1, /*A*/0, 0, 512, in_proj_w, in_proj_w, 512,
        /*C*/1, 1, 2048, nullptr, nullptr);

    // 3) causal conv + SiLU, fwd + bwd fused in one kernel
    conv_silu_kernel<<<(BL_ * DIN_) / 256, 256>>>(
        conv_w_fw, conv_b_fw, conv_w_bw, conv_b_bw);

    // 4) x_proj split-K (8 chunks of 128) x 2 branches -> partials (512 CTAs)
    gemm_tc<128, 64, 0, 1><<<dim3(1, BL_ / 128, 16), 256>>>(
        1024, 128, 8, /*A*/2, 3, 1024, xproj_w_fw, xproj_w_bw, 1024,
        0, 0, 64, nullptr, nullptr);
    reduce_split_kernel<<<(2 * BL_ * 64 / 4) / 256, 256>>>(
        8, BL_ * 64 / 4, /*dst*/4, 5);

    // 5) delta both branches fused: softplus(dt(4096,32) @ dt_w^T + b) (1024 CTAs)
    gemm_tc<128, 64, 1, 0><<<dim3(1024 / 64, BL_ / 128, 2), 256>>>(
        32, 0, 1, /*A*/4, 5, 64, dt_w_fw, dt_w_bw, 32,
        /*C*/6, 7, 1024, dt_b_fw, dt_b_bw);

    // 6) chunked selective scan: pass1 (E,P) -> stitch (H) -> pass2 (y)
    scan_chunk_kernel<1><<<dim3(DIN_ / 32, B_ * NCH_, 2), 512>>>(A_log_fw, A_log_bw);
    scan_stitch_kernel<<<(4 * SC_PER) / 256, 256>>>();
    scan_chunk_kernel<2><<<dim3(DIN_ / 32, B_ * NCH_, 2), 512>>>(A_log_fw, A_log_bw);

    // 7) combine with gate g = silu(z)
    combine_kernel<<<(BL_ * DIN_) / 256, 256>>>(D_fw, D_bw);

    // 8) out_proj split-K=2: g_yc(4096,1024) @ out_proj_w(512,1024)^T (512 CTAs)
    gemm_tc<128, 64, 0, 1><<<dim3(512 / 64, BL_ / 128, 2), 256>>>(
        1024, 512, 2, /*A*/8, 8, 1024, out_proj_w, out_proj_w, 1024,
        0, 0, 512, nullptr, nullptr);

    // 9) LN2(residual + partial0 + partial1) -> d_out  (reduce fused)
    ln_kernel<<<BL_, 128>>>(x, ln2_w, ln2_b, out, 1);
}

// round 13
// speedup vs baseline: 2.4970x; 1.1288x over previous
#include <cuda_runtime.h>
#include <cuda_bf16.h>
#include <cstdint>
#include <cstddef>

// ---------------- problem constants ----------------
constexpr int B_   = 2;
constexpr int L_   = 2048;
constexpr int DIM_ = 512;
constexpr int DIN_ = 1024;
constexpr int DST_ = 16;
constexpr int BL_  = B_ * L_;          // 4096 rows
constexpr int NCH_ = 8;                // scan chunks
constexpr int CH_  = L_ / NCH_;        // 256 steps per chunk
#define LOG2E_F 1.4426950408889634f

// ---------------- scratch (static device globals; no allocation) ----------------
__device__ __nv_bfloat16 g_xn_h [(size_t)BL_ * DIM_]; // LN1 output (bf16)
__device__ float g_ul    [(size_t)BL_ * 2 * DIN_];    // in_proj output [u | z]
__device__ float g_ucf   [(size_t)BL_ * DIN_];        // conv+silu fwd
__device__ float g_ucb   [(size_t)BL_ * DIN_];        // conv+silu bwd (reversed time)
__device__ float g_xdblf [(size_t)BL_ * 64];          // x_proj fwd [dt|B|C]
__device__ float g_xdblb [(size_t)BL_ * 64];
__device__ float g_deltaf[(size_t)BL_ * DIN_];
__device__ float g_deltab[(size_t)BL_ * DIN_];
__device__ float g_ysf   [(size_t)BL_ * DIN_];        // scan output fwd
__device__ float g_ysb   [(size_t)BL_ * DIN_];        // scan output bwd (reversed time)
__device__ __nv_bfloat16 g_yc_h[(size_t)BL_ * DIN_];  // combined y (bf16)
__device__ float g_part  [(size_t)4194304];           // split-K partials / scan states
__device__ __nv_bfloat16 g_wi_h[(size_t)2 * DIN_ * DIM_]; // in_proj_w bf16
__device__ __nv_bfloat16 g_wo_h[(size_t)DIM_ * DIN_];     // out_proj_w bf16

// scan state slabs inside g_part (free between x_proj reduce and out_proj):
constexpr size_t SC_E = 0;
constexpr size_t SC_P = 524288;
constexpr size_t SC_H = 1048576;
constexpr int SC_PER = DIN_ * DST_;    // 16384 values per (branch,batch,chunk)

__device__ __forceinline__ float* get_buf(int id) {
    switch (id) {
        case 2: return g_ucf;
        case 3: return g_ucb;
        case 4: return g_xdblf;
        case 5: return g_xdblb;
        case 6: return g_deltaf;
        default: return g_deltab;
    }
}

// ---------------- small math helpers ----------------
__device__ __forceinline__ float ex2f_(float x) {
    float y; asm("ex2.approx.ftz.f32 %0, %1;" : "=f"(y) : "f"(x)); return y;
}
__device__ __forceinline__ float silu_f(float x) {
    return x / (1.0f + ex2f_(-LOG2E_F * x));
}
__device__ __forceinline__ float softplus_f(float x) {
    return fmaxf(x, 0.0f) + log1pf(__expf(-fabsf(x)));
}
__device__ __forceinline__ void mma_tf32(float c[4], const unsigned a[4],
                                         unsigned b0, unsigned b1) {
    asm volatile(
        "mma.sync.aligned.m16n8k8.row.col.f32.tf32.tf32.f32 "
        "{%0,%1,%2,%3}, {%4,%5,%6,%7}, {%8,%9}, {%0,%1,%2,%3};"
        : "+f"(c[0]), "+f"(c[1]), "+f"(c[2]), "+f"(c[3])
        : "r"(a[0]), "r"(a[1]), "r"(a[2]), "r"(a[3]), "r"(b0), "r"(b1));
}
__device__ __forceinline__ void mma_bf16(float c[4], const unsigned a[4],
                                         unsigned b0, unsigned b1) {
    asm volatile(
        "mma.sync.aligned.m16n8k16.row.col.f32.bf16.bf16.f32 "
        "{%0,%1,%2,%3}, {%4,%5,%6,%7}, {%8,%9}, {%0,%1,%2,%3};"
        : "+f"(c[0]), "+f"(c[1]), "+f"(c[2]), "+f"(c[3])
        : "r"(a[0]), "r"(a[1]), "r"(a[2]), "r"(a[3]), "r"(b0), "r"(b1));
}
__device__ __forceinline__ void ldsm_x4(unsigned r[4], uint32_t addr) {
    asm volatile("ldmatrix.sync.aligned.m8n8.x4.shared.b16 {%0,%1,%2,%3}, [%4];"
                 : "=r"(r[0]), "=r"(r[1]), "=r"(r[2]), "=r"(r[3]) : "r"(addr));
}
__device__ __forceinline__ void cp16(uint32_t smem_dst, const void* gsrc) {
    asm volatile("cp.async.cg.shared.global [%0], [%1], 16;"
                 :: "r"(smem_dst), "l"(gsrc));
}
#define CP_COMMIT()  asm volatile("cp.async.commit_group;")
#define CP_WAIT0()   asm volatile("cp.async.wait_group 0;")

// ---------------- weight fp32 -> bf16 conversion --------------------------------
__global__ __launch_bounds__(256) void wcvt_kernel(
    const float* __restrict__ wi, const float* __restrict__ wo)
{
    const int i = blockIdx.x * 256 + threadIdx.x;
    constexpr int N1 = 2 * DIN_ * DIM_;      // 1048576
    if (i < N1) g_wi_h[i] = __float2bfloat16_rn(wi[i]);
    else        g_wo_h[i - N1] = __float2bfloat16_rn(wo[i - N1]);
}

// ---------------- LayerNorm ----------------------------------------------------
// mode 0: LN1  x -> g_xn_h (bf16)
// mode 1: LN2  (x + part0 + part1) -> out   (out_proj split-K reduce fused in)
__global__ __launch_bounds__(128) void ln_kernel(
    const float* __restrict__ x, const float* __restrict__ w,
    const float* __restrict__ bvec, float* __restrict__ outp, int mode)
{
    __shared__ float red[8];
    const int row = blockIdx.x;
    const int tid = threadIdx.x;     // 128 threads, 4 floats each (DIM=512)

    float4 v = reinterpret_cast<const float4*>(x + (size_t)row * DIM_)[tid];
    if (mode) {
        float4 r0 = reinterpret_cast<const float4*>(g_part + (size_t)row * DIM_)[tid];
        float4 r1 = reinterpret_cast<const float4*>(
                        g_part + (size_t)BL_ * DIM_ + (size_t)row * DIM_)[tid];
        v.x += r0.x + r1.x; v.y += r0.y + r1.y;
        v.z += r0.z + r1.z; v.w += r0.w + r1.w;
    }
    float s  = v.x + v.y + v.z + v.w;
    float ss = v.x*v.x + v.y*v.y + v.z*v.z + v.w*v.w;
    #pragma unroll
    for (int o = 16; o; o >>= 1) {
        s  += __shfl_xor_sync(0xffffffffu, s,  o);
        ss += __shfl_xor_sync(0xffffffffu, ss, o);
    }
    if ((tid & 31) == 0) { red[tid >> 5] = s; red[4 + (tid >> 5)] = ss; }
    __syncthreads();
    s  = red[0] + red[1] + red[2] + red[3];
    ss = red[4] + red[5] + red[6] + red[7];
    const float mean = s * (1.0f / DIM_);
    const float var  = ss * (1.0f / DIM_) - mean * mean;
    const float inv  = rsqrtf(var + 1e-5f);

    float4 wv = reinterpret_cast<const float4*>(w)[tid];
    float4 bv = reinterpret_cast<const float4*>(bvec)[tid];
    float4 o4;
    o4.x = (v.x - mean) * inv * wv.x + bv.x;
    o4.y = (v.y - mean) * inv * wv.y + bv.y;
    o4.z = (v.z - mean) * inv * wv.z + bv.z;
    o4.w = (v.w - mean) * inv * wv.w + bv.w;
    if (mode) {
        reinterpret_cast<float4*>(outp + (size_t)row * DIM_)[tid] = o4;
    } else {
        __nv_bfloat162 p0 = __floats2bfloat162_rn(o4.x, o4.y);
        __nv_bfloat162 p1 = __floats2bfloat162_rn(o4.z, o4.w);
        __nv_bfloat162* dst = reinterpret_cast<__nv_bfloat162*>(
            g_xn_h + (size_t)row * DIM_);
        dst[2 * tid]     = p0;
        dst[2 * tid + 1] = p1;
    }
}

// ---------------- bf16 tensor-core GEMM (ldmatrix + m16n8k16) -------------------
// C(M,N) = A(M,K) @ W(N,K)^T, A/W bf16, C fp32. 256 threads, 8 warps (4m x 2n).
// Block tile 128x128, BK=32, warp tile 32x64, double-buffered cp.async.
// W is [n][k] in smem: the mma B-fragment (pair along k within row n) is the
// NON-transposed ldmatrix delivery.
// MODE 0: C written directly. MODE 1: split-K, z=blockIdx.z chunk of kchunk,
//         partial to g_part[z*Mtot*ldc + ...].
template <int MODE>
__global__ __launch_bounds__(256) void gemm_bf16_kernel(
    int Kd, int kchunk,
    const __nv_bfloat16* __restrict__ A, int lda,
    const __nv_bfloat16* __restrict__ W, int ldw,
    float* __restrict__ C, int ldc)
{
    constexpr int SH = 40;                       // smem stride in halves (80B)
    __shared__ __align__(16) __nv_bfloat16 sA[2][128 * SH];
    __shared__ __align__(16) __nv_bfloat16 sW[2][128 * SH];

    const int tid  = threadIdx.x;
    const int lane = tid & 31;
    const int warp = tid >> 5;
    const int g    = lane >> 2;
    const int tig  = lane & 3;
    const int wm   = warp & 3;                   // 0..3 m-warps
    const int wn   = warp >> 2;                  // 0..1 n-warps
    const int m0   = blockIdx.y * 128;
    const int n0   = blockIdx.x * 128;
    const int Mtot = gridDim.y * 128;

    int k_begin, k_end;
    if (MODE == 1) { k_begin = blockIdx.z * kchunk; k_end = k_begin + kchunk; }
    else           { k_begin = 0; k_end = Kd; }

    const uint32_t sAb = (uint32_t)__cvta_generic_to_shared(&sA[0][0]);
    const uint32_t sWb = (uint32_t)__cvta_generic_to_shared(&sW[0][0]);

    float acc[2][8][4];
    #pragma unroll
    for (int i = 0; i < 2; i++)
        #pragma unroll
        for (int j = 0; j < 8; j++)
            #pragma unroll
            for (int q = 0; q < 4; q++) acc[i][j][q] = 0.0f;

    // staging: 2 x 16B per array per thread (128 rows x 32 halves)
    const int r_st = tid >> 2;                   // rows 0..63 (+64 on 2nd)
    const int k_st = (tid & 3) * 8;              // half-offset 0,8,16,24
    auto stage = [&](int k0, int bufi) {
        #pragma unroll
        for (int i = 0; i < 2; i++) {
            const int r = r_st + i * 64;
            const uint32_t so = (uint32_t)(bufi * 128 * SH + r * SH + k_st) * 2;
            cp16(sAb + so, A + (size_t)(m0 + r) * lda + k0 + k_st);
            cp16(sWb + so, W + (size_t)(n0 + r) * ldw + k0 + k_st);
        }
    };

    // ldmatrix source addresses (x4 grouping: m0=rows+0/k+0, m1=rows+0/k+8,
    // m2=rows+8/k+0, m3=rows+8/k+8 for B; A covers 16 rows x 16 k)
    const int a_row = wm * 32 + (lane & 15);
    const int a_col8 = (lane >> 4) * 8;
    const int b_row = wn * 64 + (lane & 7) + 8 * ((lane >> 4) & 1);
    const int b_col8 = 8 * ((lane >> 3) & 1);

    auto compute = [&](int bufi) {
        const uint32_t aBase = sAb + (uint32_t)(bufi * 128 * SH) * 2;
        const uint32_t wBase = sWb + (uint32_t)(bufi * 128 * SH) * 2;
        #pragma unroll
        for (int ks = 0; ks < 32; ks += 16) {
            unsigned af[2][4];
            #pragma unroll
            for (int im = 0; im < 2; im++)
                ldsm_x4(af[im], aBase +
                    (uint32_t)((a_row + im * 16) * SH + ks + a_col8) * 2);
            #pragma unroll
            for (int j = 0; j < 4; j++) {
                unsigned bf[4];
                ldsm_x4(bf, wBase +
                    (uint32_t)((b_row + j * 16) * SH + ks + b_col8) * 2);
                mma_bf16(acc[0][2 * j],     af[0], bf[0], bf[1]);
                mma_bf16(acc[0][2 * j + 1], af[0], bf[2], bf[3]);
                mma_bf16(acc[1][2 * j],     af[1], bf[0], bf[1]);
                mma_bf16(acc[1][2 * j + 1], af[1], bf[2], bf[3]);
            }
        }
    };

    stage(k_begin, 0);
    CP_COMMIT();
    int buf = 0;
    for (int k0 = k_begin; k0 < k_end; k0 += 32) {
        CP_WAIT0();
        __syncthreads();
        if (k0 + 32 < k_end) { stage(k0 + 32, buf ^ 1); CP_COMMIT(); }
        compute(buf);
        buf ^= 1;
        __syncthreads();
    }

    float* __restrict__ Cp =
        (MODE == 1) ? (g_part + (size_t)blockIdx.z * Mtot * ldc) : C;

    #pragma unroll
    for (int im = 0; im < 2; im++) {
        #pragma unroll
        for (int f = 0; f < 8; f++) {
            const int row = m0 + wm * 32 + im * 16 + g;
            const int col = n0 + wn * 64 + f * 8 + 2 * tig;
            *reinterpret_cast<float2*>(&Cp[(size_t)row * ldc + col]) =
                make_float2(acc[im][f][0], acc[im][f][1]);
            *reinterpret_cast<float2*>(&Cp[(size_t)(row + 8) * ldc + col]) =
                make_float2(acc[im][f][2], acc[im][f][3]);
        }
    }
}

// ---------------- tf32 tensor-core GEMM (x_proj / dt) ---------------------------
template <int BM, int BN, int EPI, int MODE>
__global__ __launch_bounds__(256) void gemm_tc(
    int Kd, int kchunk, int nsplit,
    int aid0, int aid1, int lda,
    const float* __restrict__ W0, const float* __restrict__ W1, int ldw,
    int cid0, int cid1, int ldc,
    const float* __restrict__ b0p, const float* __restrict__ b1p)
{
    constexpr int WARPS_M = BM / 32;
    constexpr int WARPS_N = 8 / WARPS_M;
    constexpr int WTN = BN / WARPS_N;
    constexpr int NF  = WTN / 8;
    constexpr int AF4 = BM / 64;
    constexpr int WF4 = BN / 64;
    constexpr int SST = 20;

    __shared__ __align__(16) float sA[2][BM * SST];
    __shared__ __align__(16) float sW[2][BN * SST];

    const int z = blockIdx.z;
    int br, k_begin, k_end;
    if (MODE == 1) { br = z / nsplit; const int ks = z - br * nsplit;
                     k_begin = ks * kchunk; k_end = k_begin + kchunk; }
    else           { br = z; k_begin = 0; k_end = Kd; }

    const float* __restrict__ A    = get_buf(br ? aid1 : aid0);
    const float* __restrict__ W    = br ? W1 : W0;
    const float* __restrict__ bias = br ? b1p : b0p;

    const int tid  = threadIdx.x;
    const int lane = tid & 31;
    const int warp = tid >> 5;
    const int g    = lane >> 2;
    const int tig  = lane & 3;
    const int wm   = warp % WARPS_M;
    const int wn   = warp / WARPS_M;
    const int m0   = blockIdx.y * BM;
    const int n0   = blockIdx.x * BN;
    const int Mtot = gridDim.y * BM;

    const uint32_t sAb = (uint32_t)__cvta_generic_to_shared(&sA[0][0]);
    const uint32_t sWb = (uint32_t)__cvta_generic_to_shared(&sW[0][0]);

    float acc[2][NF][4];
    #pragma unroll
    for (int i = 0; i < 2; i++)
        #pragma unroll
        for (int j = 0; j < NF; j++)
            #pragma unroll
            for (int q = 0; q < 4; q++) acc[i][j][q] = 0.0f;

    auto ldTileAsync = [&](int k0, int bufi) {
        #pragma unroll
        for (int i = 0; i < AF4; i++) {
            const int idx = tid + i * 256;
            const int r = idx >> 2, kk = (idx & 3) * 4;
            cp16(sAb + (uint32_t)(bufi * BM * SST + r * SST + kk) * 4,
                 A + (size_t)(m0 + r) * lda + k0 + kk);
        }
        #pragma unroll
        for (int i = 0; i < WF4; i++) {
            const int idx = tid + i * 256;
            const int r = idx >> 2, kk = (idx & 3) * 4;
            cp16(sWb + (uint32_t)(bufi * BN * SST + r * SST + kk) * 4,
                 W + (size_t)(n0 + r) * ldw + k0 + kk);
        }
    };
    auto compute = [&](int bufi) {
        const unsigned* uA = reinterpret_cast<const unsigned*>(&sA[bufi][0]);
        const unsigned* uW = reinterpret_cast<const unsigned*>(&sW[bufi][0]);
        #pragma unroll
        for (int ks = 0; ks < 16; ks += 8) {
            unsigned af[2][4];
            #pragma unroll
            for (int im = 0; im < 2; im++) {
                const int base = (wm * 32 + im * 16 + g) * SST + ks;
                af[im][0] = uA[base + tig];
                af[im][1] = uA[base + 8 * SST + tig];
                af[im][2] = uA[base + 4 + tig];
                af[im][3] = uA[base + 8 * SST + 4 + tig];
            }
            #pragma unroll
            for (int in = 0; in < NF; in++) {
                const int nb = (wn * WTN + in * 8 + g) * SST + ks;
                const unsigned bf0 = uW[nb + tig];
                const unsigned bf1 = uW[nb + 4 + tig];
                #pragma unroll
                for (int im = 0; im < 2; im++)
                    mma_tf32(acc[im][in], af[im], bf0, bf1);
            }
        }
    };

    ldTileAsync(k_begin, 0);
    CP_COMMIT();
    int buf = 0;
    for (int k0 = k_begin; k0 < k_end; k0 += 16) {
        CP_WAIT0();
        __syncthreads();
        if (k0 + 16 < k_end) { ldTileAsync(k0 + 16, buf ^ 1); CP_COMMIT(); }
        compute(buf);
        buf ^= 1;
    }

    float* __restrict__ Cp;
    if (MODE == 1) Cp = g_part + (size_t)z * (size_t)Mtot * ldc;
    else           Cp = get_buf(br ? cid1 : cid0);

    #pragma unroll
    for (int im = 0; im < 2; im++) {
        #pragma unroll
        for (int in = 0; in < NF; in++) {
            const int row = m0 + wm * 32 + im * 16 + g;
            const int col = n0 + wn * WTN + in * 8 + 2 * tig;
            float v0 = acc[im][in][0], v1 = acc[im][in][1];
            float v2 = acc[im][in][2], v3 = acc[im][in][3];
            if (EPI == 1) {
                const float bc0 = bias[col], bc1 = bias[col + 1];
                v0 = softplus_f(v0 + bc0); v1 = softplus_f(v1 + bc1);
                v2 = softplus_f(v2 + bc0); v3 = softplus_f(v3 + bc1);
            }
            *reinterpret_cast<float2*>(&Cp[(size_t)row * ldc + col])       = make_float2(v0, v1);
            *reinterpret_cast<float2*>(&Cp[(size_t)(row + 8) * ldc + col]) = make_float2(v2, v3);
        }
    }
}

// ---------------- split-K reduce (x_proj): dst[br] = sum_s part[br*nsplit+s] ----
__global__ __launch_bounds__(256) void reduce_split_kernel(
    int nsplit, int elems4, int dst0, int dst1)
{
    const int i = blockIdx.x * 256 + threadIdx.x;
    const int br = i / elems4;
    const int off = i - br * elems4;
    const float4* p = reinterpret_cast<const float4*>(g_part)
                    + (size_t)(br * nsplit) * elems4 + off;
    float4 a = p[0];
    for (int s = 1; s < nsplit; s++) {
        const float4 v = p[(size_t)s * elems4];
        a.x += v.x; a.y += v.y; a.z += v.z; a.w += v.w;
    }
    reinterpret_cast<float4*>(get_buf(br ? dst1 : dst0))[off] = a;
}

// ---------------- depthwise causal conv (K=4) + SiLU, both branches in one ------
__global__ __launch_bounds__(256) void conv_silu_kernel(
    const float* __restrict__ wf, const float* __restrict__ biasf,
    const float* __restrict__ wb, const float* __restrict__ biasb)
{
    const int i  = blockIdx.x * 256 + threadIdx.x;     // over BL*DIN
    const int d  = i & (DIN_ - 1);
    const int t  = (i >> 10) & (L_ - 1);
    const int b  = i >> 21;

    float af = biasf[d];
    float ab = biasb[d];
    #pragma unroll
    for (int k = 0; k < 4; k++) {
        const int s = t - 3 + k;
        if (s >= 0) {
            af += wf[d * 4 + k] * g_ul[((size_t)(b * L_ + s) << 11) + d];
            ab += wb[d * 4 + k] * g_ul[((size_t)(b * L_ + (L_ - 1 - s)) << 11) + d];
        }
    }
    const size_t oi = ((size_t)(b * L_ + t) << 10) + d;
    g_ucf[oi] = silu_f(af);
    g_ucb[oi] = silu_f(ab);
}

// ---------------- chunked selective scan ----------------------------------------
template <int PASS>
__global__ __launch_bounds__(512) void scan_chunk_kernel(
    const float* __restrict__ AlogF, const float* __restrict__ AlogB)
{
    const int br = blockIdx.z;
    const int b  = blockIdx.y / NCH_;
    const int ch = blockIdx.y % NCH_;
    const int d0 = blockIdx.x * 32;
    const int tid = threadIdx.x;
    const int n  = tid & 15;
    const int dl = tid >> 4;
    const int d  = d0 + dl;
    const int tbase = ch * CH_;
    const int grp = br * B_ + b;
    const size_t sidx = (size_t)(grp * NCH_ + ch) * SC_PER + d0 * DST_ + tid;

    const float* __restrict__ delta = br ? g_deltab : g_deltaf;
    const float* __restrict__ xdbl  = br ? g_xdblb  : g_xdblf;
    const float* __restrict__ uc    = br ? g_ucb    : g_ucf;
    const float* __restrict__ Alog  = br ? AlogB    : AlogF;
    float* __restrict__ ys          = br ? g_ysb    : g_ysf;

    const float AL2 = -__expf(Alog[d * DST_ + n]) * LOG2E_F;

    __shared__ __align__(16) float sdl[2][64 * 32];
    __shared__ __align__(16) float suc[2][64 * 32];
    __shared__ __align__(16) float sbc[2][64 * 32];
    __shared__ float sy[64][33];

    const uint32_t sdl_b = (uint32_t)__cvta_generic_to_shared(&sdl[0][0]);
    const uint32_t suc_b = (uint32_t)__cvta_generic_to_shared(&suc[0][0]);
    const uint32_t sbc_b = (uint32_t)__cvta_generic_to_shared(&sbc[0][0]);

    const int srow = tid >> 3;
    const int sch  = (tid & 7) * 4;
    auto stage = [&](int t0, int bufi) {
        const size_t gr = ((size_t)(b * L_ + t0 + srow) << 10) + d0 + sch;
        const uint32_t so = (uint32_t)(bufi * 2048 + srow * 32 + sch) * 4;
        cp16(sdl_b + so, delta + gr);
        cp16(suc_b + so, uc + gr);
        cp16(sbc_b + so, xdbl + (((size_t)(b * L_ + t0 + srow)) << 6) + 32 + sch);
    };

    stage(tbase, 0);
    CP_COMMIT();
    float h    = (PASS == 2) ? g_part[SC_H + sidx] : 0.0f;
    float prod = 1.0f;
    int buf = 0;

    for (int t0 = tbase; t0 < tbase + CH_; t0 += 64) {
        CP_WAIT0();
        __syncthreads();
        if (t0 + 64 < tbase + CH_) { stage(t0 + 64, buf ^ 1); CP_COMMIT(); }

        #pragma unroll 8
        for (int tt = 0; tt < 64; tt++) {
            const float dv = sdl[buf][tt * 32 + dl];
            const float uv = suc[buf][tt * 32 + dl];
            const float bb = sbc[buf][tt * 32 + n];
            const float e  = ex2f_(dv * AL2);
            h = fmaf(e, h, dv * uv * bb);
            if (PASS == 1) {
                prod *= e;
            } else {
                const float cc = sbc[buf][tt * 32 + 16 + n];
                float p = h * cc;
                p += __shfl_xor_sync(0xffffffffu, p, 1);
                p += __shfl_xor_sync(0xffffffffu, p, 2);
                p += __shfl_xor_sync(0xffffffffu, p, 4);
                p += __shfl_xor_sync(0xffffffffu, p, 8);
                if (n == 0) sy[tt][dl] = p;
            }
        }
        if (PASS == 2) {
            __syncthreads();
            #pragma unroll
            for (int i = tid; i < 64 * 32; i += 512) {
                const int tt = i >> 5, c = i & 31;
                ys[((size_t)(b * L_ + t0 + tt) << 10) + d0 + c] = sy[tt][c];
            }
        }
        buf ^= 1;
    }

    if (PASS == 1) {
        g_part[SC_E + sidx] = h;
        g_part[SC_P + sidx] = prod;
    }
}

// ---------------- stitch: H_c = P_{c-1} H_{c-1} + E_{c-1}, H_0 = 0 ---------------
__global__ __launch_bounds__(256) void scan_stitch_kernel()
{
    const int i = blockIdx.x * 256 + threadIdx.x;      // over 4 * SC_PER = 65536
    const int grp = i / SC_PER;
    const int off = i - grp * SC_PER;
    float run = 0.0f;
    #pragma unroll
    for (int c = 0; c < NCH_; c++) {
        const size_t idx = (size_t)(grp * NCH_ + c) * SC_PER + off;
        g_part[SC_H + idx] = run;
        run = g_part[SC_P + idx] * run + g_part[SC_E + idx];
    }
}

// ---------------- combine: yc = g*(ys_f + uc_f*D_f + rev(ys_b + uc_b*D_b)) ------
__global__ __launch_bounds__(256) void combine_kernel(
    const float* __restrict__ Df, const float* __restrict__ Db)
{
    const int i = blockIdx.x * 256 + threadIdx.x;      // over BL*DIN
    const int d = i & (DIN_ - 1);
    const int t = (i >> 10) & (L_ - 1);
    const int b = i >> 21;

    const float z  = g_ul[((size_t)(b * L_ + t) << 11) + DIN_ + d];
    const float gg = silu_f(z);
    const size_t fi = (size_t)i;
    const size_t bi = ((size_t)(b * L_ + (L_ - 1 - t)) << 10) + d;
    const float yf = g_ysf[fi] + g_ucf[fi] * Df[d];
    const float yr = g_ysb[bi] + g_ucb[bi] * Db[d];
    g_yc_h[fi] = __float2bfloat16_rn(gg * (yf + yr));
}

// ---------------- launch ----------------
extern "C" void kernel_launch(void* const* d_in, const int* in_sizes, int n_in,
                              void* d_out, int out_size)
{
    const float* x          = (const float*)d_in[0];
    const float* ln1_w      = (const float*)d_in[1];
    const float* ln1_b      = (const float*)d_in[2];
    const float* ln2_w      = (const float*)d_in[3];
    const float* ln2_b      = (const float*)d_in[4];
    const float* in_proj_w  = (const float*)d_in[5];
    const float* conv_w_fw  = (const float*)d_in[6];
    const float* conv_b_fw  = (const float*)d_in[7];
    const float* xproj_w_fw = (const float*)d_in[8];
    const float* dt_w_fw    = (const float*)d_in[9];
    const float* dt_b_fw    = (const float*)d_in[10];
    const float* A_log_fw   = (const float*)d_in[11];
    const float* D_fw       = (const float*)d_in[12];
    const float* conv_w_bw  = (const float*)d_in[13];
    const float* conv_b_bw  = (const float*)d_in[14];
    const float* xproj_w_bw = (const float*)d_in[15];
    const float* dt_w_bw    = (const float*)d_in[16];
    const float* dt_b_bw    = (const float*)d_in[17];
    const float* A_log_bw   = (const float*)d_in[18];
    const float* D_bw       = (const float*)d_in[19];
    const float* out_proj_w = (const float*)d_in[20];
    float* out = (float*)d_out;

    __nv_bfloat16* xn_h = nullptr;
    __nv_bfloat16* yc_h = nullptr;
    __nv_bfloat16* wi_h = nullptr;
    __nv_bfloat16* wo_h = nullptr;
    float* ul_p = nullptr;
    cudaGetSymbolAddress((void**)&xn_h, g_xn_h);
    cudaGetSymbolAddress((void**)&yc_h, g_yc_h);
    cudaGetSymbolAddress((void**)&wi_h, g_wi_h);
    cudaGetSymbolAddress((void**)&wo_h, g_wo_h);
    cudaGetSymbolAddress((void**)&ul_p, g_ul);

    // 0) weights -> bf16 (1.5M elems)
    wcvt_kernel<<<(2 * DIN_ * DIM_ + DIM_ * DIN_) / 256, 256>>>(in_proj_w, out_proj_w);

    // 1) LN1: x -> g_xn_h (bf16)
    ln_kernel<<<BL_, 128>>>(x, ln1_w, ln1_b, nullptr, 0);

    // 2) in_proj (bf16): xn(4096,512) @ wi(2048,512)^T -> g_ul (512 CTAs)
    gemm_bf16_kernel<0><<<dim3(2048 / 128, BL_ / 128, 1), 256>>>(
        512, 0, xn_h, 512, wi_h, 512, ul_p, 2048);

    // 3) causal conv + SiLU, fwd + bwd fused
    conv_silu_kernel<<<(BL_ * DIN_) / 256, 256>>>(
        conv_w_fw, conv_b_fw, conv_w_bw, conv_b_bw);

    // 4) x_proj split-K (8x128) x 2 branches (tf32) -> partials -> reduce
    gemm_tc<128, 64, 0, 1><<<dim3(1, BL_ / 128, 16), 256>>>(
        1024, 128, 8, /*A*/2, 3, 1024, xproj_w_fw, xproj_w_bw, 1024,
        0, 0, 64, nullptr, nullptr);
    reduce_split_kernel<<<(2 * BL_ * 64 / 4) / 256, 256>>>(
        8, BL_ * 64 / 4, /*dst*/4, 5);

    // 5) delta = softplus(dt @ dt_w^T + b), both branches (tf32)
    gemm_tc<128, 64, 1, 0><<<dim3(1024 / 64, BL_ / 128, 2), 256>>>(
        32, 0, 1, /*A*/4, 5, 64, dt_w_fw, dt_w_bw, 32,
        /*C*/6, 7, 1024, dt_b_fw, dt_b_bw);

    // 6) chunked selective scan: pass1 (E,P) -> stitch (H) -> pass2 (y)
    scan_chunk_kernel<1><<<dim3(DIN_ / 32, B_ * NCH_, 2), 512>>>(A_log_fw, A_log_bw);
    scan_stitch_kernel<<<(4 * SC_PER) / 256, 256>>>();
    scan_chunk_kernel<2><<<dim3(DIN_ / 32, B_ * NCH_, 2), 512>>>(A_log_fw, A_log_bw);

    // 7) combine with gate -> g_yc_h (bf16)
    combine_kernel<<<(BL_ * DIN_) / 256, 256>>>(D_fw, D_bw);

    // 8) out_proj (bf16) split-K=2: yc(4096,1024) @ wo(512,1024)^T (256 CTAs)
    gemm_bf16_kernel<1><<<dim3(512 / 128, BL_ / 128, 2), 256>>>(
        1024, 512, yc_h, 1024, wo_h, 1024, nullptr, 512);

    // 9) LN2(residual + partial0 + partial1) -> d_out  (reduce fused)
    ln_kernel<<<BL_, 128>>>(x, ln2_w, ln2_b, out, 1);
}

// round 14
// speedup vs baseline: 3.5269x; 1.4125x over previous
#include <cuda_runtime.h>
#include <cuda_bf16.h>
#include <cstdint>
#include <cstddef>

// ---------------- problem constants ----------------
constexpr int B_   = 2;
constexpr int L_   = 2048;
constexpr int DIM_ = 512;
constexpr int DIN_ = 1024;
constexpr int DST_ = 16;
constexpr int BL_  = B_ * L_;          // 4096 rows
constexpr int NCH_ = 8;                // scan chunks
constexpr int CH_  = L_ / NCH_;        // 256 steps per chunk
#define LOG2E_F 1.4426950408889634f

// ---------------- scratch (static device globals; no allocation) ----------------
__device__ __nv_bfloat16 g_xn_h [(size_t)BL_ * DIM_]; // LN1 output (bf16)
__device__ float g_ul    [(size_t)BL_ * 2 * DIN_];    // in_proj output [u | z]
__device__ float g_ucf   [(size_t)BL_ * DIN_];        // conv+silu fwd
__device__ float g_ucb   [(size_t)BL_ * DIN_];        // conv+silu bwd (reversed time)
__device__ float g_xdblf [(size_t)BL_ * 64];          // x_proj fwd [dt|B|C]
__device__ float g_xdblb [(size_t)BL_ * 64];
__device__ float g_deltaf[(size_t)BL_ * DIN_];
__device__ float g_deltab[(size_t)BL_ * DIN_];
__device__ float g_ysf   [(size_t)BL_ * DIN_];        // scan output fwd
__device__ float g_ysb   [(size_t)BL_ * DIN_];        // scan output bwd (reversed time)
__device__ __nv_bfloat16 g_yc_h[(size_t)BL_ * DIN_];  // combined y (bf16)
__device__ float g_part  [(size_t)4194304];           // split-K partials / scan states
__device__ __nv_bfloat16 g_wi_h[(size_t)2 * DIN_ * DIM_]; // in_proj_w bf16
__device__ __nv_bfloat16 g_wo_h[(size_t)DIM_ * DIN_];     // out_proj_w bf16

// scan state slabs inside g_part (free between x_proj reduce and out_proj):
constexpr size_t SC_E = 0;
constexpr size_t SC_P = 524288;
constexpr size_t SC_H = 1048576;
constexpr int SC_PER = DIN_ * DST_;    // 16384 values per (branch,batch,chunk)

__device__ __forceinline__ float* get_buf(int id) {
    switch (id) {
        case 2: return g_ucf;
        case 3: return g_ucb;
        case 4: return g_xdblf;
        case 5: return g_xdblb;
        case 6: return g_deltaf;
        default: return g_deltab;
    }
}

// ---------------- small math helpers ----------------
__device__ __forceinline__ float ex2f_(float x) {
    float y; asm("ex2.approx.ftz.f32 %0, %1;" : "=f"(y) : "f"(x)); return y;
}
__device__ __forceinline__ float silu_f(float x) {
    return x / (1.0f + ex2f_(-LOG2E_F * x));
}
__device__ __forceinline__ float softplus_f(float x) {
    return fmaxf(x, 0.0f) + log1pf(__expf(-fabsf(x)));
}
__device__ __forceinline__ void mma_tf32(float c[4], const unsigned a[4],
                                         unsigned b0, unsigned b1) {
    asm volatile(
        "mma.sync.aligned.m16n8k8.row.col.f32.tf32.tf32.f32 "
        "{%0,%1,%2,%3}, {%4,%5,%6,%7}, {%8,%9}, {%0,%1,%2,%3};"
        : "+f"(c[0]), "+f"(c[1]), "+f"(c[2]), "+f"(c[3])
        : "r"(a[0]), "r"(a[1]), "r"(a[2]), "r"(a[3]), "r"(b0), "r"(b1));
}
__device__ __forceinline__ void mma_bf16(float c[4], const unsigned a[4],
                                         unsigned b0, unsigned b1) {
    asm volatile(
        "mma.sync.aligned.m16n8k16.row.col.f32.bf16.bf16.f32 "
        "{%0,%1,%2,%3}, {%4,%5,%6,%7}, {%8,%9}, {%0,%1,%2,%3};"
        : "+f"(c[0]), "+f"(c[1]), "+f"(c[2]), "+f"(c[3])
        : "r"(a[0]), "r"(a[1]), "r"(a[2]), "r"(a[3]), "r"(b0), "r"(b1));
}
__device__ __forceinline__ void ldsm_x4(unsigned r[4], uint32_t addr) {
    asm volatile("ldmatrix.sync.aligned.m8n8.x4.shared.b16 {%0,%1,%2,%3}, [%4];"
                 : "=r"(r[0]), "=r"(r[1]), "=r"(r[2]), "=r"(r[3]) : "r"(addr));
}
__device__ __forceinline__ void cp16(uint32_t smem_dst, const void* gsrc) {
    asm volatile("cp.async.cg.shared.global [%0], [%1], 16;"
                 :: "r"(smem_dst), "l"(gsrc));
}
#define CP_COMMIT()  asm volatile("cp.async.commit_group;")
#define CP_WAIT0()   asm volatile("cp.async.wait_group 0;")

// ---------------- weight fp32 -> bf16 conversion --------------------------------
__global__ __launch_bounds__(256) void wcvt_kernel(
    const float* __restrict__ wi, const float* __restrict__ wo)
{
    const int i = blockIdx.x * 256 + threadIdx.x;
    constexpr int N1 = 2 * DIN_ * DIM_;      // 1048576
    if (i < N1) g_wi_h[i] = __float2bfloat16_rn(wi[i]);
    else        g_wo_h[i - N1] = __float2bfloat16_rn(wo[i - N1]);
}

// ---------------- LayerNorm ----------------------------------------------------
// mode 0: LN1  x -> g_xn_h (bf16)
// mode 1: LN2  (x + part0 + part1) -> out   (out_proj split-K reduce fused in)
__global__ __launch_bounds__(128) void ln_kernel(
    const float* __restrict__ x, const float* __restrict__ w,
    const float* __restrict__ bvec, float* __restrict__ outp, int mode)
{
    __shared__ float red[8];
    const int row = blockIdx.x;
    const int tid = threadIdx.x;     // 128 threads, 4 floats each (DIM=512)

    float4 v = reinterpret_cast<const float4*>(x + (size_t)row * DIM_)[tid];
    if (mode) {
        float4 r0 = reinterpret_cast<const float4*>(g_part + (size_t)row * DIM_)[tid];
        float4 r1 = reinterpret_cast<const float4*>(
                        g_part + (size_t)BL_ * DIM_ + (size_t)row * DIM_)[tid];
        v.x += r0.x + r1.x; v.y += r0.y + r1.y;
        v.z += r0.z + r1.z; v.w += r0.w + r1.w;
    }
    float s  = v.x + v.y + v.z + v.w;
    float ss = v.x*v.x + v.y*v.y + v.z*v.z + v.w*v.w;
    #pragma unroll
    for (int o = 16; o; o >>= 1) {
        s  += __shfl_xor_sync(0xffffffffu, s,  o);
        ss += __shfl_xor_sync(0xffffffffu, ss, o);
    }
    if ((tid & 31) == 0) { red[tid >> 5] = s; red[4 + (tid >> 5)] = ss; }
    __syncthreads();
    s  = red[0] + red[1] + red[2] + red[3];
    ss = red[4] + red[5] + red[6] + red[7];
    const float mean = s * (1.0f / DIM_);
    const float var  = ss * (1.0f / DIM_) - mean * mean;
    const float inv  = rsqrtf(var + 1e-5f);

    float4 wv = reinterpret_cast<const float4*>(w)[tid];
    float4 bv = reinterpret_cast<const float4*>(bvec)[tid];
    float4 o4;
    o4.x = (v.x - mean) * inv * wv.x + bv.x;
    o4.y = (v.y - mean) * inv * wv.y + bv.y;
    o4.z = (v.z - mean) * inv * wv.z + bv.z;
    o4.w = (v.w - mean) * inv * wv.w + bv.w;
    if (mode) {
        reinterpret_cast<float4*>(outp + (size_t)row * DIM_)[tid] = o4;
    } else {
        __nv_bfloat162 p0 = __floats2bfloat162_rn(o4.x, o4.y);
        __nv_bfloat162 p1 = __floats2bfloat162_rn(o4.z, o4.w);
        __nv_bfloat162* dst = reinterpret_cast<__nv_bfloat162*>(
            g_xn_h + (size_t)row * DIM_);
        dst[2 * tid]     = p0;
        dst[2 * tid + 1] = p1;
    }
}

// ---------------- bf16 tensor-core GEMM (ldmatrix + m16n8k16) -------------------
// C(M,N) = A(M,K) @ W(N,K)^T, A/W bf16, C fp32. 256 threads, 8 warps (4m x 2n).
// Block tile 128x128, BK=32, warp tile 32x64, double-buffered cp.async.
// MODE 0: C written directly. MODE 1: split-K, z=blockIdx.z chunk of kchunk,
//         partial to g_part[z*Mtot*ldc + ...].
template <int MODE>
__global__ __launch_bounds__(256) void gemm_bf16_kernel(
    int Kd, int kchunk,
    const __nv_bfloat16* __restrict__ A, int lda,
    const __nv_bfloat16* __restrict__ W, int ldw,
    float* __restrict__ C, int ldc)
{
    constexpr int SH = 40;                       // smem stride in halves (80B)
    __shared__ __align__(16) __nv_bfloat16 sA[2][128 * SH];
    __shared__ __align__(16) __nv_bfloat16 sW[2][128 * SH];

    const int tid  = threadIdx.x;
    const int lane = tid & 31;
    const int warp = tid >> 5;
    const int g    = lane >> 2;
    const int tig  = lane & 3;
    const int wm   = warp & 3;                   // 0..3 m-warps
    const int wn   = warp >> 2;                  // 0..1 n-warps
    const int m0   = blockIdx.y * 128;
    const int n0   = blockIdx.x * 128;
    const int Mtot = gridDim.y * 128;

    int k_begin, k_end;
    if (MODE == 1) { k_begin = blockIdx.z * kchunk; k_end = k_begin + kchunk; }
    else           { k_begin = 0; k_end = Kd; }

    const uint32_t sAb = (uint32_t)__cvta_generic_to_shared(&sA[0][0]);
    const uint32_t sWb = (uint32_t)__cvta_generic_to_shared(&sW[0][0]);

    float acc[2][8][4];
    #pragma unroll
    for (int i = 0; i < 2; i++)
        #pragma unroll
        for (int j = 0; j < 8; j++)
            #pragma unroll
            for (int q = 0; q < 4; q++) acc[i][j][q] = 0.0f;

    const int r_st = tid >> 2;                   // rows 0..63 (+64 on 2nd)
    const int k_st = (tid & 3) * 8;              // half-offset 0,8,16,24
    auto stage = [&](int k0, int bufi) {
        #pragma unroll
        for (int i = 0; i < 2; i++) {
            const int r = r_st + i * 64;
            const uint32_t so = (uint32_t)(bufi * 128 * SH + r * SH + k_st) * 2;
            cp16(sAb + so, A + (size_t)(m0 + r) * lda + k0 + k_st);
            cp16(sWb + so, W + (size_t)(n0 + r) * ldw + k0 + k_st);
        }
    };

    const int a_row = wm * 32 + (lane & 15);
    const int a_col8 = (lane >> 4) * 8;
    const int b_row = wn * 64 + (lane & 7) + 8 * ((lane >> 4) & 1);
    const int b_col8 = 8 * ((lane >> 3) & 1);

    auto compute = [&](int bufi) {
        const uint32_t aBase = sAb + (uint32_t)(bufi * 128 * SH) * 2;
        const uint32_t wBase = sWb + (uint32_t)(bufi * 128 * SH) * 2;
        #pragma unroll
        for (int ks = 0; ks < 32; ks += 16) {
            unsigned af[2][4];
            #pragma unroll
            for (int im = 0; im < 2; im++)
                ldsm_x4(af[im], aBase +
                    (uint32_t)((a_row + im * 16) * SH + ks + a_col8) * 2);
            #pragma unroll
            for (int j = 0; j < 4; j++) {
                unsigned bf[4];
                ldsm_x4(bf, wBase +
                    (uint32_t)((b_row + j * 16) * SH + ks + b_col8) * 2);
                mma_bf16(acc[0][2 * j],     af[0], bf[0], bf[1]);
                mma_bf16(acc[0][2 * j + 1], af[0], bf[2], bf[3]);
                mma_bf16(acc[1][2 * j],     af[1], bf[0], bf[1]);
                mma_bf16(acc[1][2 * j + 1], af[1], bf[2], bf[3]);
            }
        }
    };

    stage(k_begin, 0);
    CP_COMMIT();
    int buf = 0;
    for (int k0 = k_begin; k0 < k_end; k0 += 32) {
        CP_WAIT0();
        __syncthreads();
        if (k0 + 32 < k_end) { stage(k0 + 32, buf ^ 1); CP_COMMIT(); }
        compute(buf);
        buf ^= 1;
        __syncthreads();
    }

    float* __restrict__ Cp =
        (MODE == 1) ? (g_part + (size_t)blockIdx.z * Mtot * ldc) : C;

    #pragma unroll
    for (int im = 0; im < 2; im++) {
        #pragma unroll
        for (int f = 0; f < 8; f++) {
            const int row = m0 + wm * 32 + im * 16 + g;
            const int col = n0 + wn * 64 + f * 8 + 2 * tig;
            *reinterpret_cast<float2*>(&Cp[(size_t)row * ldc + col]) =
                make_float2(acc[im][f][0], acc[im][f][1]);
            *reinterpret_cast<float2*>(&Cp[(size_t)(row + 8) * ldc + col]) =
                make_float2(acc[im][f][2], acc[im][f][3]);
        }
    }
}

// ---------------- tf32 tensor-core GEMM (x_proj / dt) ---------------------------
template <int BM, int BN, int EPI, int MODE>
__global__ __launch_bounds__(256) void gemm_tc(
    int Kd, int kchunk, int nsplit,
    int aid0, int aid1, int lda,
    const float* __restrict__ W0, const float* __restrict__ W1, int ldw,
    int cid0, int cid1, int ldc,
    const float* __restrict__ b0p, const float* __restrict__ b1p)
{
    constexpr int WARPS_M = BM / 32;
    constexpr int WARPS_N = 8 / WARPS_M;
    constexpr int WTN = BN / WARPS_N;
    constexpr int NF  = WTN / 8;
    constexpr int AF4 = BM / 64;
    constexpr int WF4 = BN / 64;
    constexpr int SST = 20;

    __shared__ __align__(16) float sA[2][BM * SST];
    __shared__ __align__(16) float sW[2][BN * SST];

    const int z = blockIdx.z;
    int br, k_begin, k_end;
    if (MODE == 1) { br = z / nsplit; const int ks = z - br * nsplit;
                     k_begin = ks * kchunk; k_end = k_begin + kchunk; }
    else           { br = z; k_begin = 0; k_end = Kd; }

    const float* __restrict__ A    = get_buf(br ? aid1 : aid0);
    const float* __restrict__ W    = br ? W1 : W0;
    const float* __restrict__ bias = br ? b1p : b0p;

    const int tid  = threadIdx.x;
    const int lane = tid & 31;
    const int warp = tid >> 5;
    const int g    = lane >> 2;
    const int tig  = lane & 3;
    const int wm   = warp % WARPS_M;
    const int wn   = warp / WARPS_M;
    const int m0   = blockIdx.y * BM;
    const int n0   = blockIdx.x * BN;
    const int Mtot = gridDim.y * BM;

    const uint32_t sAb = (uint32_t)__cvta_generic_to_shared(&sA[0][0]);
    const uint32_t sWb = (uint32_t)__cvta_generic_to_shared(&sW[0][0]);

    float acc[2][NF][4];
    #pragma unroll
    for (int i = 0; i < 2; i++)
        #pragma unroll
        for (int j = 0; j < NF; j++)
            #pragma unroll
            for (int q = 0; q < 4; q++) acc[i][j][q] = 0.0f;

    auto ldTileAsync = [&](int k0, int bufi) {
        #pragma unroll
        for (int i = 0; i < AF4; i++) {
            const int idx = tid + i * 256;
            const int r = idx >> 2, kk = (idx & 3) * 4;
            cp16(sAb + (uint32_t)(bufi * BM * SST + r * SST + kk) * 4,
                 A + (size_t)(m0 + r) * lda + k0 + kk);
        }
        #pragma unroll
        for (int i = 0; i < WF4; i++) {
            const int idx = tid + i * 256;
            const int r = idx >> 2, kk = (idx & 3) * 4;
            cp16(sWb + (uint32_t)(bufi * BN * SST + r * SST + kk) * 4,
                 W + (size_t)(n0 + r) * ldw + k0 + kk);
        }
    };
    auto compute = [&](int bufi) {
        const unsigned* uA = reinterpret_cast<const unsigned*>(&sA[bufi][0]);
        const unsigned* uW = reinterpret_cast<const unsigned*>(&sW[bufi][0]);
        #pragma unroll
        for (int ks = 0; ks < 16; ks += 8) {
            unsigned af[2][4];
            #pragma unroll
            for (int im = 0; im < 2; im++) {
                const int base = (wm * 32 + im * 16 + g) * SST + ks;
                af[im][0] = uA[base + tig];
                af[im][1] = uA[base + 8 * SST + tig];
                af[im][2] = uA[base + 4 + tig];
                af[im][3] = uA[base + 8 * SST + 4 + tig];
            }
            #pragma unroll
            for (int in = 0; in < NF; in++) {
                const int nb = (wn * WTN + in * 8 + g) * SST + ks;
                const unsigned bf0 = uW[nb + tig];
                const unsigned bf1 = uW[nb + 4 + tig];
                #pragma unroll
                for (int im = 0; im < 2; im++)
                    mma_tf32(acc[im][in], af[im], bf0, bf1);
            }
        }
    };

    ldTileAsync(k_begin, 0);
    CP_COMMIT();
    int buf = 0;
    for (int k0 = k_begin; k0 < k_end; k0 += 16) {
        CP_WAIT0();
        __syncthreads();
        if (k0 + 16 < k_end) { ldTileAsync(k0 + 16, buf ^ 1); CP_COMMIT(); }
        compute(buf);
        buf ^= 1;
    }

    float* __restrict__ Cp;
    if (MODE == 1) Cp = g_part + (size_t)z * (size_t)Mtot * ldc;
    else           Cp = get_buf(br ? cid1 : cid0);

    #pragma unroll
    for (int im = 0; im < 2; im++) {
        #pragma unroll
        for (int in = 0; in < NF; in++) {
            const int row = m0 + wm * 32 + im * 16 + g;
            const int col = n0 + wn * WTN + in * 8 + 2 * tig;
            float v0 = acc[im][in][0], v1 = acc[im][in][1];
            float v2 = acc[im][in][2], v3 = acc[im][in][3];
            if (EPI == 1) {
                const float bc0 = bias[col], bc1 = bias[col + 1];
                v0 = softplus_f(v0 + bc0); v1 = softplus_f(v1 + bc1);
                v2 = softplus_f(v2 + bc0); v3 = softplus_f(v3 + bc1);
            }
            *reinterpret_cast<float2*>(&Cp[(size_t)row * ldc + col])       = make_float2(v0, v1);
            *reinterpret_cast<float2*>(&Cp[(size_t)(row + 8) * ldc + col]) = make_float2(v2, v3);
        }
    }
}

// ---------------- split-K reduce (x_proj): dst[br] = sum_s part[br*nsplit+s] ----
__global__ __launch_bounds__(256) void reduce_split_kernel(
    int nsplit, int elems4, int dst0, int dst1)
{
    const int i = blockIdx.x * 256 + threadIdx.x;
    const int br = i / elems4;
    const int off = i - br * elems4;
    const float4* p = reinterpret_cast<const float4*>(g_part)
                    + (size_t)(br * nsplit) * elems4 + off;
    float4 a = p[0];
    for (int s = 1; s < nsplit; s++) {
        const float4 v = p[(size_t)s * elems4];
        a.x += v.x; a.y += v.y; a.z += v.z; a.w += v.w;
    }
    reinterpret_cast<float4*>(get_buf(br ? dst1 : dst0))[off] = a;
}

// ---------------- depthwise causal conv (K=4) + SiLU, float4 over d -------------
__global__ __launch_bounds__(256) void conv_silu_kernel(
    const float* __restrict__ wf, const float* __restrict__ biasf,
    const float* __restrict__ wb, const float* __restrict__ biasb)
{
    const int i  = blockIdx.x * 256 + threadIdx.x;     // over BL*DIN/4 = 1M
    const int d4 = (i & 255) << 2;                     // channel group of 4
    const int t  = (i >> 8) & (L_ - 1);
    const int b  = i >> 19;

    float4 af = *reinterpret_cast<const float4*>(&biasf[d4]);
    float4 ab = *reinterpret_cast<const float4*>(&biasb[d4]);

    // per-channel tap weights into constant-indexed register arrays
    float wfv[4][4], wbv[4][4];
    #pragma unroll
    for (int j = 0; j < 4; j++) {
        const float4 w0 = *reinterpret_cast<const float4*>(&wf[(d4 + j) * 4]);
        const float4 w1 = *reinterpret_cast<const float4*>(&wb[(d4 + j) * 4]);
        wfv[j][0] = w0.x; wfv[j][1] = w0.y; wfv[j][2] = w0.z; wfv[j][3] = w0.w;
        wbv[j][0] = w1.x; wbv[j][1] = w1.y; wbv[j][2] = w1.z; wbv[j][3] = w1.w;
    }

    #pragma unroll
    for (int k = 0; k < 4; k++) {
        const int s = t - 3 + k;
        if (s >= 0) {
            const float4 uf = *reinterpret_cast<const float4*>(
                &g_ul[((size_t)(b * L_ + s) << 11) + d4]);
            const float4 ub = *reinterpret_cast<const float4*>(
                &g_ul[((size_t)(b * L_ + (L_ - 1 - s)) << 11) + d4]);
            af.x += wfv[0][k] * uf.x; af.y += wfv[1][k] * uf.y;
            af.z += wfv[2][k] * uf.z; af.w += wfv[3][k] * uf.w;
            ab.x += wbv[0][k] * ub.x; ab.y += wbv[1][k] * ub.y;
            ab.z += wbv[2][k] * ub.z; ab.w += wbv[3][k] * ub.w;
        }
    }
    const size_t oi = ((size_t)(b * L_ + t) << 10) + d4;
    *reinterpret_cast<float4*>(&g_ucf[oi]) =
        make_float4(silu_f(af.x), silu_f(af.y), silu_f(af.z), silu_f(af.w));
    *reinterpret_cast<float4*>(&g_ucb[oi]) =
        make_float4(silu_f(ab.x), silu_f(ab.y), silu_f(ab.z), silu_f(ab.w));
}

// ---------------- chunked selective scan (4 states per thread) -------------------
// block 256 = 64 channels x 4 state-groups; thread owns h[4] for n=4g..4g+3.
// grid (DIN/64, B*NCH, 2). State layout in g_part slabs: index = d*16 + n
// (identical to previous rounds, so the stitch kernel is unchanged).
template <int PASS>
__global__ __launch_bounds__(256) void scan_chunk_kernel(
    const float* __restrict__ AlogF, const float* __restrict__ AlogB)
{
    const int br = blockIdx.z;
    const int b  = blockIdx.y / NCH_;
    const int ch = blockIdx.y % NCH_;
    const int d0 = blockIdx.x * 64;
    const int tid = threadIdx.x;
    const int dl  = tid >> 2;          // 0..63 local channel
    const int grp = tid & 3;           // state group (4 states)
    const int d   = d0 + dl;
    const int tbase = ch * CH_;
    const int gidx = (br * B_ + b) * NCH_ + ch;
    const size_t sbase = (size_t)gidx * SC_PER + (size_t)d * DST_ + 4 * grp;

    const float* __restrict__ delta = br ? g_deltab : g_deltaf;
    const float* __restrict__ xdbl  = br ? g_xdblb  : g_xdblf;
    const float* __restrict__ uc    = br ? g_ucb    : g_ucf;
    const float* __restrict__ Alog  = br ? AlogB    : AlogF;
    float* __restrict__ ys          = br ? g_ysb    : g_ysf;

    float AL2[4];
    #pragma unroll
    for (int j = 0; j < 4; j++)
        AL2[j] = -__expf(Alog[d * DST_ + 4 * grp + j]) * LOG2E_F;

    __shared__ __align__(16) float sdl[2][32 * 64];   // [t][dl]
    __shared__ __align__(16) float suc[2][32 * 64];
    __shared__ __align__(16) float sbc[2][32 * 32];   // [t][B0..15|C0..15]
    __shared__ float sy[32][65];

    const uint32_t sdl_b = (uint32_t)__cvta_generic_to_shared(&sdl[0][0]);
    const uint32_t suc_b = (uint32_t)__cvta_generic_to_shared(&suc[0][0]);
    const uint32_t sbc_b = (uint32_t)__cvta_generic_to_shared(&sbc[0][0]);

    // staging: dv/uc 2 cp16 each, bc 1 cp16 per thread per 32-step tile
    const int r16 = tid >> 4;          // 0..15
    const int c16 = (tid & 15) * 4;    // 0..60
    const int rb  = tid >> 3;          // 0..31
    const int cb  = (tid & 7) * 4;     // 0..28
    auto stage = [&](int t0, int bufi) {
        #pragma unroll
        for (int i = 0; i < 2; i++) {
            const int row = r16 + i * 16;
            const size_t gr = ((size_t)(b * L_ + t0 + row) << 10) + d0 + c16;
            const uint32_t so = (uint32_t)(bufi * 2048 + row * 64 + c16) * 4;
            cp16(sdl_b + so, delta + gr);
            cp16(suc_b + so, uc + gr);
        }
        cp16(sbc_b + (uint32_t)(bufi * 1024 + rb * 32 + cb) * 4,
             xdbl + (((size_t)(b * L_ + t0 + rb)) << 6) + 32 + cb);
    };

    stage(tbase, 0);
    CP_COMMIT();
    float h[4]  = {0.0f, 0.0f, 0.0f, 0.0f};
    float pr[4] = {1.0f, 1.0f, 1.0f, 1.0f};
    if (PASS == 2) {
        const float4 hv = *reinterpret_cast<const float4*>(&g_part[SC_H + sbase]);
        h[0] = hv.x; h[1] = hv.y; h[2] = hv.z; h[3] = hv.w;
    }
    int buf = 0;

    for (int t0 = tbase; t0 < tbase + CH_; t0 += 32) {
        CP_WAIT0();
        __syncthreads();
        if (t0 + 32 < tbase + CH_) { stage(t0 + 32, buf ^ 1); CP_COMMIT(); }

        #pragma unroll 4
        for (int tt = 0; tt < 32; tt++) {
            const float dv = sdl[buf][tt * 64 + dl];   // broadcast per quad
            const float uv = suc[buf][tt * 64 + dl];
            const float du = dv * uv;
            const float4 b4 = *reinterpret_cast<const float4*>(
                &sbc[buf][tt * 32 + 4 * grp]);
            const float4 c4 = *reinterpret_cast<const float4*>(
                &sbc[buf][tt * 32 + 16 + 4 * grp]);
            const float e0 = ex2f_(dv * AL2[0]);
            const float e1 = ex2f_(dv * AL2[1]);
            const float e2 = ex2f_(dv * AL2[2]);
            const float e3 = ex2f_(dv * AL2[3]);
            h[0] = fmaf(e0, h[0], du * b4.x);
            h[1] = fmaf(e1, h[1], du * b4.y);
            h[2] = fmaf(e2, h[2], du * b4.z);
            h[3] = fmaf(e3, h[3], du * b4.w);
            if (PASS == 1) {
                pr[0] *= e0; pr[1] *= e1; pr[2] *= e2; pr[3] *= e3;
            } else {
                float y = h[0] * c4.x;
                y = fmaf(h[1], c4.y, y);
                y = fmaf(h[2], c4.z, y);
                y = fmaf(h[3], c4.w, y);
                y += __shfl_xor_sync(0xffffffffu, y, 1);
                y += __shfl_xor_sync(0xffffffffu, y, 2);
                if (grp == 0) sy[tt][dl] = y;
            }
        }
        if (PASS == 2) {
            __syncthreads();
            #pragma unroll
            for (int i = tid; i < 32 * 64; i += 256) {
                const int tt = i >> 6, c = i & 63;
                ys[((size_t)(b * L_ + t0 + tt) << 10) + d0 + c] = sy[tt][c];
            }
        }
        buf ^= 1;
        // next iteration's top __syncthreads orders sy reads before overwrite
    }

    if (PASS == 1) {
        *reinterpret_cast<float4*>(&g_part[SC_E + sbase]) =
            make_float4(h[0], h[1], h[2], h[3]);
        *reinterpret_cast<float4*>(&g_part[SC_P + sbase]) =
            make_float4(pr[0], pr[1], pr[2], pr[3]);
    }
}

// ---------------- stitch: H_c = P_{c-1} H_{c-1} + E_{c-1}, H_0 = 0 ---------------
__global__ __launch_bounds__(256) void scan_stitch_kernel()
{
    const int i = blockIdx.x * 256 + threadIdx.x;      // over 4 * SC_PER = 65536
    const int grp = i / SC_PER;
    const int off = i - grp * SC_PER;
    float run = 0.0f;
    #pragma unroll
    for (int c = 0; c < NCH_; c++) {
        const size_t idx = (size_t)(grp * NCH_ + c) * SC_PER + off;
        g_part[SC_H + idx] = run;
        run = g_part[SC_P + idx] * run + g_part[SC_E + idx];
    }
}

// ---------------- combine (float4): yc = g*(ys_f + uc_f*D_f + rev(...)) ---------
__global__ __launch_bounds__(256) void combine_kernel(
    const float* __restrict__ Df, const float* __restrict__ Db)
{
    const int i  = blockIdx.x * 256 + threadIdx.x;     // over BL*DIN/4 = 1M
    const int d4 = (i & 255) << 2;
    const int t  = (i >> 8) & (L_ - 1);
    const int b  = i >> 19;

    const size_t fi = ((size_t)(b * L_ + t) << 10) + d4;
    const size_t bi = ((size_t)(b * L_ + (L_ - 1 - t)) << 10) + d4;

    const float4 z  = *reinterpret_cast<const float4*>(
        &g_ul[((size_t)(b * L_ + t) << 11) + DIN_ + d4]);
    const float4 dfv = *reinterpret_cast<const float4*>(&Df[d4]);
    const float4 dbv = *reinterpret_cast<const float4*>(&Db[d4]);
    const float4 yF = *reinterpret_cast<const float4*>(&g_ysf[fi]);
    const float4 uF = *reinterpret_cast<const float4*>(&g_ucf[fi]);
    const float4 yB = *reinterpret_cast<const float4*>(&g_ysb[bi]);
    const float4 uB = *reinterpret_cast<const float4*>(&g_ucb[bi]);

    const float r0 = silu_f(z.x) * (yF.x + uF.x * dfv.x + yB.x + uB.x * dbv.x);
    const float r1 = silu_f(z.y) * (yF.y + uF.y * dfv.y + yB.y + uB.y * dbv.y);
    const float r2 = silu_f(z.z) * (yF.z + uF.z * dfv.z + yB.z + uB.z * dbv.z);
    const float r3 = silu_f(z.w) * (yF.w + uF.w * dfv.w + yB.w + uB.w * dbv.w);

    __nv_bfloat162* dst = reinterpret_cast<__nv_bfloat162*>(&g_yc_h[fi]);
    dst[0] = __floats2bfloat162_rn(r0, r1);
    dst[1] = __floats2bfloat162_rn(r2, r3);
}

// ---------------- launch ----------------
extern "C" void kernel_launch(void* const* d_in, const int* in_sizes, int n_in,
                              void* d_out, int out_size)
{
    const float* x          = (const float*)d_in[0];
    const float* ln1_w      = (const float*)d_in[1];
    const float* ln1_b      = (const float*)d_in[2];
    const float* ln2_w      = (const float*)d_in[3];
    const float* ln2_b      = (const float*)d_in[4];
    const float* in_proj_w  = (const float*)d_in[5];
    const float* conv_w_fw  = (const float*)d_in[6];
    const float* conv_b_fw  = (const float*)d_in[7];
    const float* xproj_w_fw = (const float*)d_in[8];
    const float* dt_w_fw    = (const float*)d_in[9];
    const float* dt_b_fw    = (const float*)d_in[10];
    const float* A_log_fw   = (const float*)d_in[11];
    const float* D_fw       = (const float*)d_in[12];
    const float* conv_w_bw  = (const float*)d_in[13];
    const float* conv_b_bw  = (const float*)d_in[14];
    const float* xproj_w_bw = (const float*)d_in[15];
    const float* dt_w_bw    = (const float*)d_in[16];
    const float* dt_b_bw    = (const float*)d_in[17];
    const float* A_log_bw   = (const float*)d_in[18];
    const float* D_bw       = (const float*)d_in[19];
    const float* out_proj_w = (const float*)d_in[20];
    float* out = (float*)d_out;

    __nv_bfloat16* xn_h = nullptr;
    __nv_bfloat16* yc_h = nullptr;
    __nv_bfloat16* wi_h = nullptr;
    __nv_bfloat16* wo_h = nullptr;
    float* ul_p = nullptr;
    cudaGetSymbolAddress((void**)&xn_h, g_xn_h);
    cudaGetSymbolAddress((void**)&yc_h, g_yc_h);
    cudaGetSymbolAddress((void**)&wi_h, g_wi_h);
    cudaGetSymbolAddress((void**)&wo_h, g_wo_h);
    cudaGetSymbolAddress((void**)&ul_p, g_ul);

    // 0) weights -> bf16 (1.5M elems)
    wcvt_kernel<<<(2 * DIN_ * DIM_ + DIM_ * DIN_) / 256, 256>>>(in_proj_w, out_proj_w);

    // 1) LN1: x -> g_xn_h (bf16)
    ln_kernel<<<BL_, 128>>>(x, ln1_w, ln1_b, nullptr, 0);

    // 2) in_proj (bf16): xn(4096,512) @ wi(2048,512)^T -> g_ul (512 CTAs)
    gemm_bf16_kernel<0><<<dim3(2048 / 128, BL_ / 128, 1), 256>>>(
        512, 0, xn_h, 512, wi_h, 512, ul_p, 2048);

    // 3) causal conv + SiLU, fwd + bwd fused, float4 over d
    conv_silu_kernel<<<(BL_ * DIN_ / 4) / 256, 256>>>(
        conv_w_fw, conv_b_fw, conv_w_bw, conv_b_bw);

    // 4) x_proj split-K (8x128) x 2 branches (tf32) -> partials -> reduce
    gemm_tc<128, 64, 0, 1><<<dim3(1, BL_ / 128, 16), 256>>>(
        1024, 128, 8, /*A*/2, 3, 1024, xproj_w_fw, xproj_w_bw, 1024,
        0, 0, 64, nullptr, nullptr);
    reduce_split_kernel<<<(2 * BL_ * 64 / 4) / 256, 256>>>(
        8, BL_ * 64 / 4, /*dst*/4, 5);

    // 5) delta = softplus(dt @ dt_w^T + b), both branches (tf32)
    gemm_tc<128, 64, 1, 0><<<dim3(1024 / 64, BL_ / 128, 2), 256>>>(
        32, 0, 1, /*A*/4, 5, 64, dt_w_fw, dt_w_bw, 32,
        /*C*/6, 7, 1024, dt_b_fw, dt_b_bw);

    // 6) chunked selective scan: pass1 (E,P) -> stitch (H) -> pass2 (y)
    scan_chunk_kernel<1><<<dim3(DIN_ / 64, B_ * NCH_, 2), 256>>>(A_log_fw, A_log_bw);
    scan_stitch_kernel<<<(4 * SC_PER) / 256, 256>>>();
    scan_chunk_kernel<2><<<dim3(DIN_ / 64, B_ * NCH_, 2), 256>>>(A_log_fw, A_log_bw);

    // 7) combine with gate -> g_yc_h (bf16), float4
    combine_kernel<<<(BL_ * DIN_ / 4) / 256, 256>>>(D_fw, D_bw);

    // 8) out_proj (bf16) split-K=2: yc(4096,1024) @ wo(512,1024)^T (256 CTAs)
    gemm_bf16_kernel<1><<<dim3(512 / 128, BL_ / 128, 2), 256>>>(
        1024, 512, yc_h, 1024, wo_h, 1024, nullptr, 512);

    // 9) LN2(residual + partial0 + partial1) -> d_out  (reduce fused)
    ln_kernel<<<BL_, 128>>>(x, ln2_w, ln2_b, out, 1);
}

// round 16
// speedup vs baseline: 3.9106x; 1.1088x over previous
#include <cuda_runtime.h>
#include <cuda_bf16.h>
#include <cstdint>
#include <cstddef>

// ---------------- problem constants ----------------
constexpr int B_   = 2;
constexpr int L_   = 2048;
constexpr int DIM_ = 512;
constexpr int DIN_ = 1024;
constexpr int DST_ = 16;
constexpr int BL_  = B_ * L_;          // 4096 rows
constexpr int NCH_ = 8;                // scan chunks
constexpr int CH_  = L_ / NCH_;        // 256 steps per chunk
#define LOG2E_F 1.4426950408889634f

// ---------------- scratch (static device globals; no allocation) ----------------
__device__ __nv_bfloat16 g_xn_h [(size_t)BL_ * DIM_]; // LN1 output (bf16)
__device__ float g_ul    [(size_t)BL_ * 2 * DIN_];    // in_proj output [u | z]
__device__ float g_ucf   [(size_t)BL_ * DIN_];        // conv+silu fwd
__device__ float g_ucb   [(size_t)BL_ * DIN_];        // conv+silu bwd (reversed time)
__device__ float g_xdblf [(size_t)BL_ * 64];          // x_proj fwd [dt|B|C]
__device__ float g_xdblb [(size_t)BL_ * 64];
__device__ float g_deltaf[(size_t)BL_ * DIN_];
__device__ float g_deltab[(size_t)BL_ * DIN_];
__device__ float g_ysf   [(size_t)BL_ * DIN_];        // scan output fwd
__device__ float g_ysb   [(size_t)BL_ * DIN_];        // scan output bwd (reversed time)
__device__ __nv_bfloat16 g_yc_h[(size_t)BL_ * DIN_];  // combined y (bf16)
__device__ float g_part  [(size_t)4194304];           // split-K partials / scan states
__device__ __nv_bfloat16 g_wi_h[(size_t)2 * DIN_ * DIM_]; // in_proj_w bf16
__device__ __nv_bfloat16 g_wo_h[(size_t)DIM_ * DIN_];     // out_proj_w bf16

// scan state slabs inside g_part (free between x_proj reduce and out_proj):
constexpr size_t SC_E = 0;
constexpr size_t SC_P = 524288;
constexpr size_t SC_H = 1048576;
constexpr int SC_PER = DIN_ * DST_;    // 16384 values per (branch,batch,chunk)

__device__ __forceinline__ float* get_buf(int id) {
    switch (id) {
        case 2: return g_ucf;
        case 3: return g_ucb;
        case 4: return g_xdblf;
        case 5: return g_xdblb;
        case 6: return g_deltaf;
        default: return g_deltab;
    }
}

// ---------------- small math helpers ----------------
__device__ __forceinline__ float ex2f_(float x) {
    float y; asm("ex2.approx.ftz.f32 %0, %1;" : "=f"(y) : "f"(x)); return y;
}
__device__ __forceinline__ float silu_f(float x) {
    return x / (1.0f + ex2f_(-LOG2E_F * x));
}
__device__ __forceinline__ float softplus_f(float x) {
    return fmaxf(x, 0.0f) + log1pf(__expf(-fabsf(x)));
}
__device__ __forceinline__ void mma_tf32(float c[4], const unsigned a[4],
                                         unsigned b0, unsigned b1) {
    asm volatile(
        "mma.sync.aligned.m16n8k8.row.col.f32.tf32.tf32.f32 "
        "{%0,%1,%2,%3}, {%4,%5,%6,%7}, {%8,%9}, {%0,%1,%2,%3};"
        : "+f"(c[0]), "+f"(c[1]), "+f"(c[2]), "+f"(c[3])
        : "r"(a[0]), "r"(a[1]), "r"(a[2]), "r"(a[3]), "r"(b0), "r"(b1));
}
__device__ __forceinline__ void mma_bf16(float c[4], const unsigned a[4],
                                         unsigned b0, unsigned b1) {
    asm volatile(
        "mma.sync.aligned.m16n8k16.row.col.f32.bf16.bf16.f32 "
        "{%0,%1,%2,%3}, {%4,%5,%6,%7}, {%8,%9}, {%0,%1,%2,%3};"
        : "+f"(c[0]), "+f"(c[1]), "+f"(c[2]), "+f"(c[3])
        : "r"(a[0]), "r"(a[1]), "r"(a[2]), "r"(a[3]), "r"(b0), "r"(b1));
}
__device__ __forceinline__ void ldsm_x4(unsigned r[4], uint32_t addr) {
    asm volatile("ldmatrix.sync.aligned.m8n8.x4.shared.b16 {%0,%1,%2,%3}, [%4];"
                 : "=r"(r[0]), "=r"(r[1]), "=r"(r[2]), "=r"(r[3]) : "r"(addr));
}
__device__ __forceinline__ void cp16(uint32_t smem_dst, const void* gsrc) {
    asm volatile("cp.async.cg.shared.global [%0], [%1], 16;"
                 :: "r"(smem_dst), "l"(gsrc));
}
#define CP_COMMIT()  asm volatile("cp.async.commit_group;")
#define CP_WAIT0()   asm volatile("cp.async.wait_group 0;")

// ---------------- weight fp32 -> bf16 conversion --------------------------------
__global__ __launch_bounds__(256) void wcvt_kernel(
    const float* __restrict__ wi, const float* __restrict__ wo)
{
    const int i = blockIdx.x * 256 + threadIdx.x;
    constexpr int N1 = 2 * DIN_ * DIM_;      // 1048576
    if (i < N1) g_wi_h[i] = __float2bfloat16_rn(wi[i]);
    else        g_wo_h[i - N1] = __float2bfloat16_rn(wo[i - N1]);
}

// ---------------- LayerNorm ----------------------------------------------------
// mode 0: LN1  x -> g_xn_h (bf16)
// mode 1: LN2  (x + part0 + part1) -> out   (out_proj split-K reduce fused in)
__global__ __launch_bounds__(128) void ln_kernel(
    const float* __restrict__ x, const float* __restrict__ w,
    const float* __restrict__ bvec, float* __restrict__ outp, int mode)
{
    __shared__ float red[8];
    const int row = blockIdx.x;
    const int tid = threadIdx.x;     // 128 threads, 4 floats each (DIM=512)

    float4 v = reinterpret_cast<const float4*>(x + (size_t)row * DIM_)[tid];
    if (mode) {
        float4 r0 = reinterpret_cast<const float4*>(g_part + (size_t)row * DIM_)[tid];
        float4 r1 = reinterpret_cast<const float4*>(
                        g_part + (size_t)BL_ * DIM_ + (size_t)row * DIM_)[tid];
        v.x += r0.x + r1.x; v.y += r0.y + r1.y;
        v.z += r0.z + r1.z; v.w += r0.w + r1.w;
    }
    float s  = v.x + v.y + v.z + v.w;
    float ss = v.x*v.x + v.y*v.y + v.z*v.z + v.w*v.w;
    #pragma unroll
    for (int o = 16; o; o >>= 1) {
        s  += __shfl_xor_sync(0xffffffffu, s,  o);
        ss += __shfl_xor_sync(0xffffffffu, ss, o);
    }
    if ((tid & 31) == 0) { red[tid >> 5] = s; red[4 + (tid >> 5)] = ss; }
    __syncthreads();
    s  = red[0] + red[1] + red[2] + red[3];
    ss = red[4] + red[5] + red[6] + red[7];
    const float mean = s * (1.0f / DIM_);
    const float var  = ss * (1.0f / DIM_) - mean * mean;
    const float inv  = rsqrtf(var + 1e-5f);

    float4 wv = reinterpret_cast<const float4*>(w)[tid];
    float4 bv = reinterpret_cast<const float4*>(bvec)[tid];
    float4 o4;
    o4.x = (v.x - mean) * inv * wv.x + bv.x;
    o4.y = (v.y - mean) * inv * wv.y + bv.y;
    o4.z = (v.z - mean) * inv * wv.z + bv.z;
    o4.w = (v.w - mean) * inv * wv.w + bv.w;
    if (mode) {
        reinterpret_cast<float4*>(outp + (size_t)row * DIM_)[tid] = o4;
    } else {
        __nv_bfloat162 p0 = __floats2bfloat162_rn(o4.x, o4.y);
        __nv_bfloat162 p1 = __floats2bfloat162_rn(o4.z, o4.w);
        __nv_bfloat162* dst = reinterpret_cast<__nv_bfloat162*>(
            g_xn_h + (size_t)row * DIM_);
        dst[2 * tid]     = p0;
        dst[2 * tid + 1] = p1;
    }
}

// ---------------- bf16 tensor-core GEMM (ldmatrix + m16n8k16) -------------------
// C(M,N) = A(M,K) @ W(N,K)^T, A/W bf16, C fp32. 256 threads, 8 warps (4m x 2n).
// Block tile 128x128, BK=32, warp tile 32x64, double-buffered cp.async.
// MODE 0: C written directly. MODE 1: split-K, z=blockIdx.z chunk of kchunk,
//         partial to g_part[z*Mtot*ldc + ...].
template <int MODE>
__global__ __launch_bounds__(256) void gemm_bf16_kernel(
    int Kd, int kchunk,
    const __nv_bfloat16* __restrict__ A, int lda,
    const __nv_bfloat16* __restrict__ W, int ldw,
    float* __restrict__ C, int ldc)
{
    constexpr int SH = 40;                       // smem stride in halves (80B)
    __shared__ __align__(16) __nv_bfloat16 sA[2][128 * SH];
    __shared__ __align__(16) __nv_bfloat16 sW[2][128 * SH];

    const int tid  = threadIdx.x;
    const int lane = tid & 31;
    const int warp = tid >> 5;
    const int g    = lane >> 2;
    const int tig  = lane & 3;
    const int wm   = warp & 3;                   // 0..3 m-warps
    const int wn   = warp >> 2;                  // 0..1 n-warps
    const int m0   = blockIdx.y * 128;
    const int n0   = blockIdx.x * 128;
    const int Mtot = gridDim.y * 128;

    int k_begin, k_end;
    if (MODE == 1) { k_begin = blockIdx.z * kchunk; k_end = k_begin + kchunk; }
    else           { k_begin = 0; k_end = Kd; }

    const uint32_t sAb = (uint32_t)__cvta_generic_to_shared(&sA[0][0]);
    const uint32_t sWb = (uint32_t)__cvta_generic_to_shared(&sW[0][0]);

    float acc[2][8][4];
    #pragma unroll
    for (int i = 0; i < 2; i++)
        #pragma unroll
        for (int j = 0; j < 8; j++)
            #pragma unroll
            for (int q = 0; q < 4; q++) acc[i][j][q] = 0.0f;

    const int r_st = tid >> 2;                   // rows 0..63 (+64 on 2nd)
    const int k_st = (tid & 3) * 8;              // half-offset 0,8,16,24
    auto stage = [&](int k0, int bufi) {
        #pragma unroll
        for (int i = 0; i < 2; i++) {
            const int r = r_st + i * 64;
            const uint32_t so = (uint32_t)(bufi * 128 * SH + r * SH + k_st) * 2;
            cp16(sAb + so, A + (size_t)(m0 + r) * lda + k0 + k_st);
            cp16(sWb + so, W + (size_t)(n0 + r) * ldw + k0 + k_st);
        }
    };

    const int a_row = wm * 32 + (lane & 15);
    const int a_col8 = (lane >> 4) * 8;
    const int b_row = wn * 64 + (lane & 7) + 8 * ((lane >> 4) & 1);
    const int b_col8 = 8 * ((lane >> 3) & 1);

    auto compute = [&](int bufi) {
        const uint32_t aBase = sAb + (uint32_t)(bufi * 128 * SH) * 2;
        const uint32_t wBase = sWb + (uint32_t)(bufi * 128 * SH) * 2;
        #pragma unroll
        for (int ks = 0; ks < 32; ks += 16) {
            unsigned af[2][4];
            #pragma unroll
            for (int im = 0; im < 2; im++)
                ldsm_x4(af[im], aBase +
                    (uint32_t)((a_row + im * 16) * SH + ks + a_col8) * 2);
            #pragma unroll
            for (int j = 0; j < 4; j++) {
                unsigned bf[4];
                ldsm_x4(bf, wBase +
                    (uint32_t)((b_row + j * 16) * SH + ks + b_col8) * 2);
                mma_bf16(acc[0][2 * j],     af[0], bf[0], bf[1]);
                mma_bf16(acc[0][2 * j + 1], af[0], bf[2], bf[3]);
                mma_bf16(acc[1][2 * j],     af[1], bf[0], bf[1]);
                mma_bf16(acc[1][2 * j + 1], af[1], bf[2], bf[3]);
            }
        }
    };

    stage(k_begin, 0);
    CP_COMMIT();
    int buf = 0;
    for (int k0 = k_begin; k0 < k_end; k0 += 32) {
        CP_WAIT0();
        __syncthreads();
        if (k0 + 32 < k_end) { stage(k0 + 32, buf ^ 1); CP_COMMIT(); }
        compute(buf);
        buf ^= 1;
        __syncthreads();
    }

    float* __restrict__ Cp =
        (MODE == 1) ? (g_part + (size_t)blockIdx.z * Mtot * ldc) : C;

    #pragma unroll
    for (int im = 0; im < 2; im++) {
        #pragma unroll
        for (int f = 0; f < 8; f++) {
            const int row = m0 + wm * 32 + im * 16 + g;
            const int col = n0 + wn * 64 + f * 8 + 2 * tig;
            *reinterpret_cast<float2*>(&Cp[(size_t)row * ldc + col]) =
                make_float2(acc[im][f][0], acc[im][f][1]);
            *reinterpret_cast<float2*>(&Cp[(size_t)(row + 8) * ldc + col]) =
                make_float2(acc[im][f][2], acc[im][f][3]);
        }
    }
}

// ---------------- tf32 tensor-core GEMM (x_proj / dt) ---------------------------
template <int BM, int BN, int EPI, int MODE>
__global__ __launch_bounds__(256) void gemm_tc(
    int Kd, int kchunk, int nsplit,
    int aid0, int aid1, int lda,
    const float* __restrict__ W0, const float* __restrict__ W1, int ldw,
    int cid0, int cid1, int ldc,
    const float* __restrict__ b0p, const float* __restrict__ b1p)
{
    constexpr int WARPS_M = BM / 32;
    constexpr int WARPS_N = 8 / WARPS_M;
    constexpr int WTN = BN / WARPS_N;
    constexpr int NF  = WTN / 8;
    constexpr int AF4 = BM / 64;
    constexpr int WF4 = BN / 64;
    constexpr int SST = 20;

    __shared__ __align__(16) float sA[2][BM * SST];
    __shared__ __align__(16) float sW[2][BN * SST];

    const int z = blockIdx.z;
    int br, k_begin, k_end;
    if (MODE == 1) { br = z / nsplit; const int ks = z - br * nsplit;
                     k_begin = ks * kchunk; k_end = k_begin + kchunk; }
    else           { br = z; k_begin = 0; k_end = Kd; }

    const float* __restrict__ A    = get_buf(br ? aid1 : aid0);
    const float* __restrict__ W    = br ? W1 : W0;
    const float* __restrict__ bias = br ? b1p : b0p;

    const int tid  = threadIdx.x;
    const int lane = tid & 31;
    const int warp = tid >> 5;
    const int g    = lane >> 2;
    const int tig  = lane & 3;
    const int wm   = warp % WARPS_M;
    const int wn   = warp / WARPS_M;
    const int m0   = blockIdx.y * BM;
    const int n0   = blockIdx.x * BN;
    const int Mtot = gridDim.y * BM;

    const uint32_t sAb = (uint32_t)__cvta_generic_to_shared(&sA[0][0]);
    const uint32_t sWb = (uint32_t)__cvta_generic_to_shared(&sW[0][0]);

    float acc[2][NF][4];
    #pragma unroll
    for (int i = 0; i < 2; i++)
        #pragma unroll
        for (int j = 0; j < NF; j++)
            #pragma unroll
            for (int q = 0; q < 4; q++) acc[i][j][q] = 0.0f;

    auto ldTileAsync = [&](int k0, int bufi) {
        #pragma unroll
        for (int i = 0; i < AF4; i++) {
            const int idx = tid + i * 256;
            const int r = idx >> 2, kk = (idx & 3) * 4;
            cp16(sAb + (uint32_t)(bufi * BM * SST + r * SST + kk) * 4,
                 A + (size_t)(m0 + r) * lda + k0 + kk);
        }
        #pragma unroll
        for (int i = 0; i < WF4; i++) {
            const int idx = tid + i * 256;
            const int r = idx >> 2, kk = (idx & 3) * 4;
            cp16(sWb + (uint32_t)(bufi * BN * SST + r * SST + kk) * 4,
                 W + (size_t)(n0 + r) * ldw + k0 + kk);
        }
    };
    auto compute = [&](int bufi) {
        const unsigned* uA = reinterpret_cast<const unsigned*>(&sA[bufi][0]);
        const unsigned* uW = reinterpret_cast<const unsigned*>(&sW[bufi][0]);
        #pragma unroll
        for (int ks = 0; ks < 16; ks += 8) {
            unsigned af[2][4];
            #pragma unroll
            for (int im = 0; im < 2; im++) {
                const int base = (wm * 32 + im * 16 + g) * SST + ks;
                af[im][0] = uA[base + tig];
                af[im][1] = uA[base + 8 * SST + tig];
                af[im][2] = uA[base + 4 + tig];
                af[im][3] = uA[base + 8 * SST + 4 + tig];
            }
            #pragma unroll
            for (int in = 0; in < NF; in++) {
                const int nb = (wn * WTN + in * 8 + g) * SST + ks;
                const unsigned bf0 = uW[nb + tig];
                const unsigned bf1 = uW[nb + 4 + tig];
                #pragma unroll
                for (int im = 0; im < 2; im++)
                    mma_tf32(acc[im][in], af[im], bf0, bf1);
            }
        }
    };

    ldTileAsync(k_begin, 0);
    CP_COMMIT();
    int buf = 0;
    for (int k0 = k_begin; k0 < k_end; k0 += 16) {
        CP_WAIT0();
        __syncthreads();
        if (k0 + 16 < k_end) { ldTileAsync(k0 + 16, buf ^ 1); CP_COMMIT(); }
        compute(buf);
        buf ^= 1;
    }

    float* __restrict__ Cp;
    if (MODE == 1) Cp = g_part + (size_t)z * (size_t)Mtot * ldc;
    else           Cp = get_buf(br ? cid1 : cid0);

    #pragma unroll
    for (int im = 0; im < 2; im++) {
        #pragma unroll
        for (int in = 0; in < NF; in++) {
            const int row = m0 + wm * 32 + im * 16 + g;
            const int col = n0 + wn * WTN + in * 8 + 2 * tig;
            float v0 = acc[im][in][0], v1 = acc[im][in][1];
            float v2 = acc[im][in][2], v3 = acc[im][in][3];
            if (EPI == 1) {
                const float bc0 = bias[col], bc1 = bias[col + 1];
                v0 = softplus_f(v0 + bc0); v1 = softplus_f(v1 + bc1);
                v2 = softplus_f(v2 + bc0); v3 = softplus_f(v3 + bc1);
            }
            *reinterpret_cast<float2*>(&Cp[(size_t)row * ldc + col])       = make_float2(v0, v1);
            *reinterpret_cast<float2*>(&Cp[(size_t)(row + 8) * ldc + col]) = make_float2(v2, v3);
        }
    }
}

// ---------------- split-K reduce (x_proj): dst[br] = sum_s part[br*nsplit+s] ----
__global__ __launch_bounds__(256) void reduce_split_kernel(
    int nsplit, int elems4, int dst0, int dst1)
{
    const int i = blockIdx.x * 256 + threadIdx.x;
    const int br = i / elems4;
    const int off = i - br * elems4;
    const float4* p = reinterpret_cast<const float4*>(g_part)
                    + (size_t)(br * nsplit) * elems4 + off;
    float4 a = p[0];
    for (int s = 1; s < nsplit; s++) {
        const float4 v = p[(size_t)s * elems4];
        a.x += v.x; a.y += v.y; a.z += v.z; a.w += v.w;
    }
    reinterpret_cast<float4*>(get_buf(br ? dst1 : dst0))[off] = a;
}

// ---------------- depthwise causal conv (K=4) + SiLU -----------------------------
// Thread computes a 4-timestep x 4-channel block with a 7-row sliding window:
// loads per output drop 2.3x vs one-timestep-per-thread (L1tex was the limiter).
__global__ __launch_bounds__(256) void conv_silu_kernel(
    const float* __restrict__ wf, const float* __restrict__ biasf,
    const float* __restrict__ wb, const float* __restrict__ biasb)
{
    const int i  = blockIdx.x * 256 + threadIdx.x;     // over B*(L/4)*(DIN/4)
    const int d4 = (i & 255) << 2;                     // channel quad
    const int t0 = ((i >> 8) & 511) << 2;              // timestep quad base
    const int b  = i >> 17;

    #pragma unroll
    for (int br = 0; br < 2; br++) {
        const float* __restrict__ wp = br ? wb : wf;
        const float4 bias4 = *reinterpret_cast<const float4*>(
            (br ? biasb : biasf) + d4);

        float w[4][4];
        #pragma unroll
        for (int j = 0; j < 4; j++) {
            const float4 wv = *reinterpret_cast<const float4*>(&wp[(d4 + j) * 4]);
            w[j][0] = wv.x; w[j][1] = wv.y; w[j][2] = wv.z; w[j][3] = wv.w;
        }

        float4 u[7];
        #pragma unroll
        for (int j = 0; j < 7; j++) {
            const int s = t0 - 3 + j;
            if (s >= 0) {
                const int row = br ? (L_ - 1 - s) : s;
                u[j] = *reinterpret_cast<const float4*>(
                    &g_ul[((size_t)(b * L_ + row) << 11) + d4]);
            } else {
                u[j] = make_float4(0.0f, 0.0f, 0.0f, 0.0f);
            }
        }

        float* __restrict__ outp = br ? g_ucb : g_ucf;
        #pragma unroll
        for (int k = 0; k < 4; k++) {
            float4 a = bias4;
            #pragma unroll
            for (int tap = 0; tap < 4; tap++) {
                const float4 uv = u[k + tap];
                a.x = fmaf(w[0][tap], uv.x, a.x);
                a.y = fmaf(w[1][tap], uv.y, a.y);
                a.z = fmaf(w[2][tap], uv.z, a.z);
                a.w = fmaf(w[3][tap], uv.w, a.w);
            }
            *reinterpret_cast<float4*>(
                &outp[((size_t)(b * L_ + t0 + k) << 10) + d4]) =
                make_float4(silu_f(a.x), silu_f(a.y), silu_f(a.z), silu_f(a.w));
        }
    }
}

// ---------------- chunked selective scan (4 states per thread) -------------------
// block 256 = 64 channels x 4 state-groups; thread owns h[4] for n=4g..4g+3.
// grid (DIN/64, B*NCH, 2). State layout: index = d*16 + n (stitch unchanged).
template <int PASS>
__global__ __launch_bounds__(256) void scan_chunk_kernel(
    const float* __restrict__ AlogF, const float* __restrict__ AlogB)
{
    const int br = blockIdx.z;
    const int b  = blockIdx.y / NCH_;
    const int ch = blockIdx.y % NCH_;
    const int d0 = blockIdx.x * 64;
    const int tid = threadIdx.x;
    const int dl  = tid >> 2;          // 0..63 local channel
    const int grp = tid & 3;           // state group (4 states)
    const int d   = d0 + dl;
    const int tbase = ch * CH_;
    const int gidx = (br * B_ + b) * NCH_ + ch;
    const size_t sbase = (size_t)gidx * SC_PER + (size_t)d * DST_ + 4 * grp;

    const float* __restrict__ delta = br ? g_deltab : g_deltaf;
    const float* __restrict__ xdbl  = br ? g_xdblb  : g_xdblf;
    const float* __restrict__ uc    = br ? g_ucb    : g_ucf;
    const float* __restrict__ Alog  = br ? AlogB    : AlogF;
    float* __restrict__ ys          = br ? g_ysb    : g_ysf;

    float AL2[4];
    #pragma unroll
    for (int j = 0; j < 4; j++)
        AL2[j] = -__expf(Alog[d * DST_ + 4 * grp + j]) * LOG2E_F;

    __shared__ __align__(16) float sdl[2][32 * 64];   // [t][dl]
    __shared__ __align__(16) float suc[2][32 * 64];
    __shared__ __align__(16) float sbc[2][32 * 32];   // [t][B0..15|C0..15]
    __shared__ float sy[32][65];

    const uint32_t sdl_b = (uint32_t)__cvta_generic_to_shared(&sdl[0][0]);
    const uint32_t suc_b = (uint32_t)__cvta_generic_to_shared(&suc[0][0]);
    const uint32_t sbc_b = (uint32_t)__cvta_generic_to_shared(&sbc[0][0]);

    const int r16 = tid >> 4;          // 0..15
    const int c16 = (tid & 15) * 4;    // 0..60
    const int rb  = tid >> 3;          // 0..31
    const int cb  = (tid & 7) * 4;     // 0..28
    auto stage = [&](int t0, int bufi) {
        #pragma unroll
        for (int i = 0; i < 2; i++) {
            const int row = r16 + i * 16;
            const size_t gr = ((size_t)(b * L_ + t0 + row) << 10) + d0 + c16;
            const uint32_t so = (uint32_t)(bufi * 2048 + row * 64 + c16) * 4;
            cp16(sdl_b + so, delta + gr);
            cp16(suc_b + so, uc + gr);
        }
        cp16(sbc_b + (uint32_t)(bufi * 1024 + rb * 32 + cb) * 4,
             xdbl + (((size_t)(b * L_ + t0 + rb)) << 6) + 32 + cb);
    };

    stage(tbase, 0);
    CP_COMMIT();
    float h[4]  = {0.0f, 0.0f, 0.0f, 0.0f};
    float pr[4] = {1.0f, 1.0f, 1.0f, 1.0f};
    if (PASS == 2) {
        const float4 hv = *reinterpret_cast<const float4*>(&g_part[SC_H + sbase]);
        h[0] = hv.x; h[1] = hv.y; h[2] = hv.z; h[3] = hv.w;
    }
    int buf = 0;

    for (int t0 = tbase; t0 < tbase + CH_; t0 += 32) {
        CP_WAIT0();
        __syncthreads();
        if (t0 + 32 < tbase + CH_) { stage(t0 + 32, buf ^ 1); CP_COMMIT(); }

        #pragma unroll 4
        for (int tt = 0; tt < 32; tt++) {
            const float dv = sdl[buf][tt * 64 + dl];
            const float uv = suc[buf][tt * 64 + dl];
            const float du = dv * uv;
            const float4 b4 = *reinterpret_cast<const float4*>(
                &sbc[buf][tt * 32 + 4 * grp]);
            const float4 c4 = *reinterpret_cast<const float4*>(
                &sbc[buf][tt * 32 + 16 + 4 * grp]);
            const float e0 = ex2f_(dv * AL2[0]);
            const float e1 = ex2f_(dv * AL2[1]);
            const float e2 = ex2f_(dv * AL2[2]);
            const float e3 = ex2f_(dv * AL2[3]);
            h[0] = fmaf(e0, h[0], du * b4.x);
            h[1] = fmaf(e1, h[1], du * b4.y);
            h[2] = fmaf(e2, h[2], du * b4.z);
            h[3] = fmaf(e3, h[3], du * b4.w);
            if (PASS == 1) {
                pr[0] *= e0; pr[1] *= e1; pr[2] *= e2; pr[3] *= e3;
            } else {
                float y = h[0] * c4.x;
                y = fmaf(h[1], c4.y, y);
                y = fmaf(h[2], c4.z, y);
                y = fmaf(h[3], c4.w, y);
                y += __shfl_xor_sync(0xffffffffu, y, 1);
                y += __shfl_xor_sync(0xffffffffu, y, 2);
                if (grp == 0) sy[tt][dl] = y;
            }
        }
        if (PASS == 2) {
            __syncthreads();
            #pragma unroll
            for (int i = tid; i < 32 * 64; i += 256) {
                const int tt = i >> 6, c = i & 63;
                ys[((size_t)(b * L_ + t0 + tt) << 10) + d0 + c] = sy[tt][c];
            }
        }
        buf ^= 1;
    }

    if (PASS == 1) {
        *reinterpret_cast<float4*>(&g_part[SC_E + sbase]) =
            make_float4(h[0], h[1], h[2], h[3]);
        *reinterpret_cast<float4*>(&g_part[SC_P + sbase]) =
            make_float4(pr[0], pr[1], pr[2], pr[3]);
    }
}

// ---------------- stitch: H_c = P_{c-1} H_{c-1} + E_{c-1}, H_0 = 0 ---------------
__global__ __launch_bounds__(256) void scan_stitch_kernel()
{
    const int i = blockIdx.x * 256 + threadIdx.x;      // over 4 * SC_PER = 65536
    const int grp = i / SC_PER;
    const int off = i - grp * SC_PER;
    float run = 0.0f;
    #pragma unroll
    for (int c = 0; c < NCH_; c++) {
        const size_t idx = (size_t)(grp * NCH_ + c) * SC_PER + off;
        g_part[SC_H + idx] = run;
        run = g_part[SC_P + idx] * run + g_part[SC_E + idx];
    }
}

// ---------------- combine (float4): yc = g*(ys_f + uc_f*D_f + rev(...)) ---------
__global__ __launch_bounds__(256) void combine_kernel(
    const float* __restrict__ Df, const float* __restrict__ Db)
{
    const int i  = blockIdx.x * 256 + threadIdx.x;     // over BL*DIN/4 = 1M
    const int d4 = (i & 255) << 2;
    const int t  = (i >> 8) & (L_ - 1);
    const int b  = i >> 19;

    const size_t fi = ((size_t)(b * L_ + t) << 10) + d4;
    const size_t bi = ((size_t)(b * L_ + (L_ - 1 - t)) << 10) + d4;

    const float4 z  = *reinterpret_cast<const float4*>(
        &g_ul[((size_t)(b * L_ + t) << 11) + DIN_ + d4]);
    const float4 dfv = *reinterpret_cast<const float4*>(&Df[d4]);
    const float4 dbv = *reinterpret_cast<const float4*>(&Db[d4]);
    const float4 yF = *reinterpret_cast<const float4*>(&g_ysf[fi]);
    const float4 uF = *reinterpret_cast<const float4*>(&g_ucf[fi]);
    const float4 yB = *reinterpret_cast<const float4*>(&g_ysb[bi]);
    const float4 uB = *reinterpret_cast<const float4*>(&g_ucb[bi]);

    const float r0 = silu_f(z.x) * (yF.x + uF.x * dfv.x + yB.x + uB.x * dbv.x);
    const float r1 = silu_f(z.y) * (yF.y + uF.y * dfv.y + yB.y + uB.y * dbv.y);
    const float r2 = silu_f(z.z) * (yF.z + uF.z * dfv.z + yB.z + uB.z * dbv.z);
    const float r3 = silu_f(z.w) * (yF.w + uF.w * dfv.w + yB.w + uB.w * dbv.w);

    __nv_bfloat162* dst = reinterpret_cast<__nv_bfloat162*>(&g_yc_h[fi]);
    dst[0] = __floats2bfloat162_rn(r0, r1);
    dst[1] = __floats2bfloat162_rn(r2, r3);
}

// ---------------- launch ----------------
extern "C" void kernel_launch(void* const* d_in, const int* in_sizes, int n_in,
                              void* d_out, int out_size)
{
    const float* x          = (const float*)d_in[0];
    const float* ln1_w      = (const float*)d_in[1];
    const float* ln1_b      = (const float*)d_in[2];
    const float* ln2_w      = (const float*)d_in[3];
    const float* ln2_b      = (const float*)d_in[4];
    const float* in_proj_w  = (const float*)d_in[5];
    const float* conv_w_fw  = (const float*)d_in[6];
    const float* conv_b_fw  = (const float*)d_in[7];
    const float* xproj_w_fw = (const float*)d_in[8];
    const float* dt_w_fw    = (const float*)d_in[9];
    const float* dt_b_fw    = (const float*)d_in[10];
    const float* A_log_fw   = (const float*)d_in[11];
    const float* D_fw       = (const float*)d_in[12];
    const float* conv_w_bw  = (const float*)d_in[13];
    const float* conv_b_bw  = (const float*)d_in[14];
    const float* xproj_w_bw = (const float*)d_in[15];
    const float* dt_w_bw    = (const float*)d_in[16];
    const float* dt_b_bw    = (const float*)d_in[17];
    const float* A_log_bw   = (const float*)d_in[18];
    const float* D_bw       = (const float*)d_in[19];
    const float* out_proj_w = (const float*)d_in[20];
    float* out = (float*)d_out;

    __nv_bfloat16* xn_h = nullptr;
    __nv_bfloat16* yc_h = nullptr;
    __nv_bfloat16* wi_h = nullptr;
    __nv_bfloat16* wo_h = nullptr;
    float* ul_p = nullptr;
    cudaGetSymbolAddress((void**)&xn_h, g_xn_h);
    cudaGetSymbolAddress((void**)&yc_h, g_yc_h);
    cudaGetSymbolAddress((void**)&wi_h, g_wi_h);
    cudaGetSymbolAddress((void**)&wo_h, g_wo_h);
    cudaGetSymbolAddress((void**)&ul_p, g_ul);

    // 0) weights -> bf16 (1.5M elems)
    wcvt_kernel<<<(2 * DIN_ * DIM_ + DIM_ * DIN_) / 256, 256>>>(in_proj_w, out_proj_w);

    // 1) LN1: x -> g_xn_h (bf16)
    ln_kernel<<<BL_, 128>>>(x, ln1_w, ln1_b, nullptr, 0);

    // 2) in_proj (bf16): xn(4096,512) @ wi(2048,512)^T -> g_ul (512 CTAs)
    gemm_bf16_kernel<0><<<dim3(2048 / 128, BL_ / 128, 1), 256>>>(
        512, 0, xn_h, 512, wi_h, 512, ul_p, 2048);

    // 3) causal conv + SiLU, 4t x 4d blocks with sliding window
    conv_silu_kernel<<<(B_ * (L_ / 4) * (DIN_ / 4)) / 256, 256>>>(
        conv_w_fw, conv_b_fw, conv_w_bw, conv_b_bw);

    // 4) x_proj split-K (8x128) x 2 branches (tf32) -> partials -> reduce
    gemm_tc<128, 64, 0, 1><<<dim3(1, BL_ / 128, 16), 256>>>(
        1024, 128, 8, /*A*/2, 3, 1024, xproj_w_fw, xproj_w_bw, 1024,
        0, 0, 64, nullptr, nullptr);
    reduce_split_kernel<<<(2 * BL_ * 64 / 4) / 256, 256>>>(
        8, BL_ * 64 / 4, /*dst*/4, 5);

    // 5) delta = softplus(dt @ dt_w^T + b), both branches (tf32)
    gemm_tc<128, 64, 1, 0><<<dim3(1024 / 64, BL_ / 128, 2), 256>>>(
        32, 0, 1, /*A*/4, 5, 64, dt_w_fw, dt_w_bw, 32,
        /*C*/6, 7, 1024, dt_b_fw, dt_b_bw);

    // 6) chunked selective scan: pass1 (E,P) -> stitch (H) -> pass2 (y)
    scan_chunk_kernel<1><<<dim3(DIN_ / 64, B_ * NCH_, 2), 256>>>(A_log_fw, A_log_bw);
    scan_stitch_kernel<<<(4 * SC_PER) / 256, 256>>>();
    scan_chunk_kernel<2><<<dim3(DIN_ / 64, B_ * NCH_, 2), 256>>>(A_log_fw, A_log_bw);

    // 7) combine with gate -> g_yc_h (bf16), float4
    combine_kernel<<<(BL_ * DIN_ / 4) / 256, 256>>>(D_fw, D_bw);

    // 8) out_proj (bf16) split-K=2: yc(4096,1024) @ wo(512,1024)^T (256 CTAs)
    gemm_bf16_kernel<1><<<dim3(512 / 128, BL_ / 128, 2), 256>>>(
        1024, 512, yc_h, 1024, wo_h, 1024, nullptr, 512);

    // 9) LN2(residual + partial0 + partial1) -> d_out  (reduce fused)
    ln_kernel<<<BL_, 128>>>(x, ln2_w, ln2_b, out, 1);
}